// round 14
// baseline (speedup 1.0000x reference)
#include <cuda_runtime.h>
#include <cuda_bf16.h>
#include <cuda_fp16.h>
#include <math.h>
#include <stdint.h>

#define S_LEN 128
#define BATCH 256
#define EDIM  256
#define HDIM  512
#define H3    1536
#define VOCAB 32000
#define ROWS  (S_LEN*BATCH)   /* 32768 */
#define XDIM  2304
#define GDIM  2048
#define NKC   6
#define NCTS  6               /* scorer col tiles of 256 */
#define KENC  1024

// ------------------------- device scratch ---------------------------------
__device__ __half g_encf[(size_t)ROWS*KENC];     // fp16 enc
__device__ __half g_w1f[H3*KENC];                // fp16 W1[:, :1024]
__device__ __half g_w1kh[H3*HDIM];               // W1[:, 1024:] hi
__device__ __half g_w1kl[H3*HDIM];               // W1[:, 1024:] lo
__device__ __half g_h0h[BATCH*HDIM];             // h0 hi
__device__ __half g_h0l[BATCH*HDIM];             // h0 lo
__device__ __half g_owf[(size_t)VOCAB*HDIM];     // fp16 out_W
__device__ __half g_hf[BATCH*HDIM];              // fp16 h_new
__device__ __half g_gwh[(size_t)GDIM*XDIM];      // gates W hi (Wih|Whh concat)
__device__ __half g_gwl[(size_t)GDIM*XDIM];      // gates W lo
__device__ __half g_xh[BATCH*XDIM];              // x hi
__device__ __half g_xl[BATCH*XDIM];              // x lo
__device__ float g_hpb[BATCH*H3];          // b1 + h0 @ W1[:,1024:]^T  per (b,m)
__device__ float g_scorep[NCTS*ROWS];
__device__ float g_gatesp[NKC*BATCH*GDIM];

__device__ __forceinline__ float sigmf(float x){ return 1.0f/(1.0f+expf(-x)); }

// single-MUFU tanh (sm_75+ base ISA), max abs err ~4.9e-4
__device__ __forceinline__ float tanh_fast(float x){
    float y;
    asm("tanh.approx.f32 %0, %1;" : "=f"(y) : "f"(x));
    return y;
}

// ------------------------- mma.sync helpers -------------------------------
__device__ __forceinline__ void cpasync16(uint32_t dst, const void* src){
    asm volatile("cp.async.cg.shared.global [%0], [%1], 16;"
        :: "r"(dst), "l"(__cvta_generic_to_global(src)));
}
__device__ __forceinline__ void cp_commit(){ asm volatile("cp.async.commit_group;"); }

__device__ __forceinline__ void ldsm4(uint32_t* r, uint32_t addr){
    asm volatile("ldmatrix.sync.aligned.m8n8.x4.shared.b16 {%0,%1,%2,%3}, [%4];"
        : "=r"(r[0]), "=r"(r[1]), "=r"(r[2]), "=r"(r[3]) : "r"(addr));
}
__device__ __forceinline__ void mma16816h(float* d, const uint32_t* a, const uint32_t* b){
    asm volatile("mma.sync.aligned.m16n8k16.row.col.f32.f16.f16.f32 "
        "{%0,%1,%2,%3}, {%4,%5,%6,%7}, {%8,%9}, {%0,%1,%2,%3};"
        : "+f"(d[0]), "+f"(d[1]), "+f"(d[2]), "+f"(d[3])
        : "r"(a[0]), "r"(a[1]), "r"(a[2]), "r"(a[3]), "r"(b[0]), "r"(b[1]));
}

// 8-wide fp16 convert helpers (16B stores)
__device__ __forceinline__ uint4 cvt8_f16(float4 v0, float4 v1){
    __half h[8] = {__float2half_rn(v0.x), __float2half_rn(v0.y),
                   __float2half_rn(v0.z), __float2half_rn(v0.w),
                   __float2half_rn(v1.x), __float2half_rn(v1.y),
                   __float2half_rn(v1.z), __float2half_rn(v1.w)};
    return *reinterpret_cast<uint4*>(h);
}
__device__ __forceinline__ void cvt8_hl(float4 v0, float4 v1, uint4& uh, uint4& ul){
    float f[8] = {v0.x, v0.y, v0.z, v0.w, v1.x, v1.y, v1.z, v1.w};
    __half h[8], l[8];
#pragma unroll
    for (int q = 0; q < 8; q++){
        h[q] = __float2half_rn(f[q]);
        l[q] = __float2half_rn(f[q] - __half2float(h[q]));
    }
    uh = *reinterpret_cast<uint4*>(h);
    ul = *reinterpret_cast<uint4*>(l);
}
__device__ __forceinline__ void store4_hl(__half* dh, __half* dl, float4 v){
    float f[4] = {v.x, v.y, v.z, v.w};
    __half h[4], l[4];
#pragma unroll
    for (int q = 0; q < 4; q++){
        h[q] = __float2half_rn(f[q]);
        l[q] = __float2half_rn(f[q] - __half2float(h[q]));
    }
    *reinterpret_cast<uint2*>(dh) = *reinterpret_cast<uint2*>(h);
    *reinterpret_cast<uint2*>(dl) = *reinterpret_cast<uint2*>(l);
}

// ============================================================================
// Shared 64x64-warp-tile chunk compute (8 warps: 2 warp_m x 4 warp_n).
// A frags prefetched for both s-iters, B double-buffered. KC=32.
// ============================================================================
#define SC_STAGE 24576

__device__ __forceinline__ void sc_chunk(uint32_t buf, int warp_m, int warp_n,
                                         int lane, float acc[4][8][4])
{
    uint32_t a[2][4][4];
#pragma unroll
    for (int s = 0; s < 2; ++s)
#pragma unroll
        for (int mt = 0; mt < 4; ++mt){
            int row = warp_m*64 + mt*16 + ((lane>>3)&1)*8 + (lane&7);
            int chunk = 2*s + (lane>>4);
            ldsm4(a[s][mt], buf + row*64 + ((uint32_t)(chunk ^ (row&3)) << 4));
        }

    uint32_t b[2][4];
    {   // first B fragment (s=0, g=0)
        int nrow = warp_n*64 + 0*16 + ((lane>>4)<<3) + (lane&7);
        int chunk = 0 + ((lane>>3)&1);
        ldsm4(b[0], buf + 8192 + nrow*64 + ((uint32_t)(chunk ^ (nrow&3)) << 4));
    }
#pragma unroll
    for (int k = 0; k < 8; ++k){
        int s = k >> 2, g = k & 3;
        if (k < 7){
            int kn = k + 1, sn = kn >> 2, gn = kn & 3;
            int nrow = warp_n*64 + gn*16 + ((lane>>4)<<3) + (lane&7);
            int chunk = 2*sn + ((lane>>3)&1);
            ldsm4(b[(k+1)&1], buf + 8192 + nrow*64 + ((uint32_t)(chunk ^ (nrow&3)) << 4));
        }
        const uint32_t* bc = b[k&1];
#pragma unroll
        for (int mt = 0; mt < 4; ++mt){
            mma16816h(acc[mt][2*g+0], a[s][mt], bc+0);
            mma16816h(acc[mt][2*g+1], a[s][mt], bc+2);
        }
    }
}

// ============================================================================
// Scorer: fp16 MMA, 256 threads / 8 warps, CTA tile 128x256.
// 8-stage ring, 2 chunks/iter (16 iters), lookahead 6, wait_group 2.
// Race-free: stage target (2p+6)%8 == 2(p-1)%8, reads done before this
// iteration's __syncthreads.
// ============================================================================
#define SC_NSTG  8
#define SC_SMEM  (SC_NSTG*SC_STAGE)
#define LG_NSTG  6
#define LG_SMEM  (LG_NSTG*SC_STAGE)

__device__ __forceinline__ void sc_stage(int row0, int col0, int k0,
                                         uint32_t smb, int tid)
{
#pragma unroll
    for (int rep = 0; rep < 6; ++rep){
        int idx = tid + rep*256;
        if (idx < 512){
            int row = idx >> 2, c = idx & 3;
            uint32_t off = row*64 + ((uint32_t)(c ^ (row & 3)) << 4);
            cpasync16(smb + off, g_encf + (size_t)(row0 + row)*KENC + k0 + c*8);
        } else {
            int j = idx - 512;
            int row = j >> 2, c = j & 3;
            uint32_t off = 8192 + row*64 + ((uint32_t)(c ^ (row & 3)) << 4);
            cpasync16(smb + off, g_w1f + (size_t)(col0 + row)*KENC + k0 + c*8);
        }
    }
}

__global__ __launch_bounds__(256,1) void scorer_fp16(const float* __restrict__ w2)
{
    extern __shared__ char smem[];
    uint32_t smu = (uint32_t)__cvta_generic_to_shared(smem);
    const int tid = threadIdx.x, lane = tid & 31, wid = tid >> 5;
    const int warp_m = wid & 1, warp_n = wid >> 1;   // 2 x 4 warps, tile 64x64
    const int row0 = blockIdx.y * 128, col0 = blockIdx.x * 256;

    float acc[4][8][4];
#pragma unroll
    for (int a = 0; a < 4; a++)
#pragma unroll
        for (int b = 0; b < 8; b++)
#pragma unroll
            for (int c = 0; c < 4; c++) acc[a][b][c] = 0.f;

    // prologue: 3 groups of 2 chunks (chunks 0..5)
    sc_stage(row0, col0,  0, smu + 0*SC_STAGE, tid);
    sc_stage(row0, col0, 32, smu + 1*SC_STAGE, tid);
    cp_commit();
    sc_stage(row0, col0, 64, smu + 2*SC_STAGE, tid);
    sc_stage(row0, col0, 96, smu + 3*SC_STAGE, tid);
    cp_commit();
    sc_stage(row0, col0, 128, smu + 4*SC_STAGE, tid);
    sc_stage(row0, col0, 160, smu + 5*SC_STAGE, tid);
    cp_commit();

    for (int p = 0; p < 16; ++p){
        asm volatile("cp.async.wait_group 2;");
        __syncthreads();
        sc_chunk(smu + ((2*p    ) & 7)*SC_STAGE, warp_m, warp_n, lane, acc);
        sc_chunk(smu + ((2*p + 1) & 7)*SC_STAGE, warp_m, warp_n, lane, acc);
        if (p + 3 < 16){
            int c0 = 2*p + 6, c1 = 2*p + 7;
            sc_stage(row0, col0, c0*32, smu + (c0 & 7)*SC_STAGE, tid);
            sc_stage(row0, col0, c1*32, smu + (c1 & 7)*SC_STAGE, tid);
        }
        cp_commit();   // empty group when no stage issued: keeps wait count exact
    }

    // epilogue: per-row w2-weighted tanh reduction over this CTA's 256 cols
    __syncthreads();
    float* sred = (float*)smem;
#pragma unroll
    for (int mt = 0; mt < 4; ++mt){
#pragma unroll
        for (int h = 0; h < 2; ++h){
            int row_local = warp_m*64 + mt*16 + h*8 + (lane>>2);
            int m0 = row0 + row_local;
            const float* hp = g_hpb + (size_t)(m0 & 255) * H3;
            float rs = 0.f;
#pragma unroll
            for (int nt = 0; nt < 8; ++nt){
                int nc = col0 + warp_n*64 + nt*8 + 2*(lane&3);
                rs += w2[nc]   * tanh_fast(acc[mt][nt][2*h+0] + hp[nc])
                    + w2[nc+1] * tanh_fast(acc[mt][nt][2*h+1] + hp[nc+1]);
            }
            rs += __shfl_xor_sync(0xffffffffu, rs, 1);
            rs += __shfl_xor_sync(0xffffffffu, rs, 2);
            if ((lane & 3) == 0) sred[warp_n*128 + row_local] = rs;
        }
    }
    __syncthreads();
    if (tid < 128)
        g_scorep[(size_t)blockIdx.x * ROWS + row0 + tid] =
            sred[tid] + sred[128 + tid] + sred[256 + tid] + sred[384 + tid];
}

// ============================================================================
// Logits: fp16 mma, CTA 128x256, 6 stages, TWO chunks/iter (8 iters, K=512).
// ============================================================================
__device__ __forceinline__ void lg_stage(int row0, int col0, int k0,
                                         uint32_t smb, int tid)
{
#pragma unroll
    for (int rep = 0; rep < 6; ++rep){
        int idx = tid + rep*256;
        if (idx < 512){
            int row = idx >> 2, c = idx & 3;
            uint32_t off = row*64 + ((uint32_t)(c ^ (row & 3)) << 4);
            cpasync16(smb + off, g_hf + (size_t)(row0 + row)*HDIM + k0 + c*8);
        } else {
            int j = idx - 512;
            int row = j >> 2, c = j & 3;
            uint32_t off = 8192 + row*64 + ((uint32_t)(c ^ (row & 3)) << 4);
            cpasync16(smb + off, g_owf + (size_t)(col0 + row)*HDIM + k0 + c*8);
        }
    }
}

__global__ __launch_bounds__(256,1) void logits_fp16(const float* __restrict__ ob,
                                                     float* __restrict__ out)
{
    extern __shared__ char smem[];
    uint32_t smu = (uint32_t)__cvta_generic_to_shared(smem);
    const int tid = threadIdx.x, lane = tid & 31, wid = tid >> 5;
    const int warp_m = wid & 1, warp_n = wid >> 1;   // 2 x 4 warps, tile 64x64
    const int row0 = blockIdx.x * 128, col0 = blockIdx.y * 256;

    float acc[4][8][4];
#pragma unroll
    for (int a = 0; a < 4; a++)
#pragma unroll
        for (int b = 0; b < 8; b++)
#pragma unroll
            for (int c = 0; c < 4; c++) acc[a][b][c] = 0.f;

    lg_stage(row0, col0,  0, smu + 0*SC_STAGE, tid);
    lg_stage(row0, col0, 32, smu + 1*SC_STAGE, tid);
    cp_commit();
    lg_stage(row0, col0, 64, smu + 2*SC_STAGE, tid);
    lg_stage(row0, col0, 96, smu + 3*SC_STAGE, tid);
    cp_commit();

    for (int p = 0; p < 8; ++p){
        asm volatile("cp.async.wait_group 1;");
        __syncthreads();
        sc_chunk(smu + ((2*p    ) % LG_NSTG)*SC_STAGE, warp_m, warp_n, lane, acc);
        sc_chunk(smu + ((2*p + 1) % LG_NSTG)*SC_STAGE, warp_m, warp_n, lane, acc);
        if (p + 2 < 8){
            int c0 = 2*p + 4, c1 = 2*p + 5;
            lg_stage(row0, col0, c0*32, smu + (c0 % LG_NSTG)*SC_STAGE, tid);
            lg_stage(row0, col0, c1*32, smu + (c1 % LG_NSTG)*SC_STAGE, tid);
        }
        cp_commit();
    }

#pragma unroll
    for (int mt = 0; mt < 4; ++mt){
#pragma unroll
        for (int h = 0; h < 2; ++h){
            int m = row0 + warp_m*64 + mt*16 + h*8 + (lane>>2);
#pragma unroll
            for (int nt = 0; nt < 8; ++nt){
                int c = col0 + warp_n*64 + nt*8 + 2*(lane&3);
                float2 v = make_float2(acc[mt][nt][2*h+0] + ob[c],
                                       acc[mt][nt][2*h+1] + ob[c+1]);
                *(float2*)(out + (size_t)m * VOCAB + c) = v;
            }
        }
    }
}

// ============================================================================
// Gates: fp16 hi/lo 3-term MMA. CTA 128x128, split-K=6 (chunks of 384).
// ============================================================================
#define GT_STAGE 32768
#define GT_SMEM  (2*GT_STAGE)

__device__ __forceinline__ void gt_stage(int row0, int col0, int k0,
                                         uint32_t smb, int tid)
{
#pragma unroll
    for (int rep = 0; rep < 2; ++rep){
        int idx = tid + rep*256;
        int row = idx >> 2, c = idx & 3;
        uint32_t off = row*64 + ((uint32_t)(c ^ (row & 3)) << 4);
        size_t ea = (size_t)(row0 + row)*XDIM + k0 + c*8;
        size_t eb = (size_t)(col0 + row)*XDIM + k0 + c*8;
        cpasync16(smb +         off, g_xh  + ea);
        cpasync16(smb +  8192 + off, g_xl  + ea);
        cpasync16(smb + 16384 + off, g_gwh + eb);
        cpasync16(smb + 24576 + off, g_gwl + eb);
    }
}

__global__ __launch_bounds__(256,1) void gates_mma()
{
    extern __shared__ char smem[];
    uint32_t smu = (uint32_t)__cvta_generic_to_shared(smem);
    const int tid = threadIdx.x, lane = tid & 31, wid = tid >> 5;
    const int warp_m = wid & 3, warp_n = wid >> 2;  // 4 x 2, warp tile 32x64
    const int row0 = blockIdx.x * 128, col0 = blockIdx.y * 128;
    const int kbeg = blockIdx.z * (XDIM / NKC);     // 384 per chunk

    float acc[2][8][4];
#pragma unroll
    for (int a = 0; a < 2; a++)
#pragma unroll
        for (int b = 0; b < 8; b++)
#pragma unroll
            for (int c = 0; c < 4; c++) acc[a][b][c] = 0.f;

    gt_stage(row0, col0, kbeg, smu, tid); cp_commit();
    const int nit = (XDIM / NKC) / 32;   // 12
    for (int it = 0; it < nit; ++it){
        if (it + 1 < nit){
            gt_stage(row0, col0, kbeg + (it+1)*32, smu + ((it+1)&1)*GT_STAGE, tid);
            cp_commit();
            asm volatile("cp.async.wait_group 1;");
        } else {
            asm volatile("cp.async.wait_group 0;");
        }
        __syncthreads();
        uint32_t buf = smu + (it&1)*GT_STAGE;
#pragma unroll
        for (int s = 0; s < 2; ++s){
            uint32_t ah[2][4], al[2][4];
#pragma unroll
            for (int mt = 0; mt < 2; ++mt){
                int row = warp_m*32 + mt*16 + ((lane>>3)&1)*8 + (lane&7);
                int chunk = 2*s + (lane>>4);
                uint32_t addr = buf + row*64 + ((uint32_t)(chunk ^ (row&3)) << 4);
                ldsm4(ah[mt], addr);
                ldsm4(al[mt], addr + 8192);
            }
#pragma unroll
            for (int g = 0; g < 4; ++g){
                int nrow = warp_n*64 + g*16 + ((lane>>4)<<3) + (lane&7);
                int chunk = 2*s + ((lane>>3)&1);
                uint32_t baddr = buf + 16384 + nrow*64 + ((uint32_t)(chunk ^ (nrow&3)) << 4);
                uint32_t bh[4], bl[4];
                ldsm4(bh, baddr);
                ldsm4(bl, baddr + 8192);
#pragma unroll
                for (int mt = 0; mt < 2; ++mt){
                    mma16816h(acc[mt][2*g+0], ah[mt], bh+0);
                    mma16816h(acc[mt][2*g+0], ah[mt], bl+0);
                    mma16816h(acc[mt][2*g+0], al[mt], bh+0);
                    mma16816h(acc[mt][2*g+1], ah[mt], bh+2);
                    mma16816h(acc[mt][2*g+1], ah[mt], bl+2);
                    mma16816h(acc[mt][2*g+1], al[mt], bh+2);
                }
            }
        }
        __syncthreads();
    }

#pragma unroll
    for (int mt = 0; mt < 2; ++mt){
        int m = row0 + warp_m*32 + mt*16 + (lane>>2);
#pragma unroll
        for (int nt = 0; nt < 8; ++nt){
            int c = col0 + warp_n*64 + nt*8 + 2*(lane&3);
            float* d0 = g_gatesp + ((size_t)blockIdx.z * BATCH + m) * GDIM + c;
            float* d1 = g_gatesp + ((size_t)blockIdx.z * BATCH + m + 8) * GDIM + c;
            d0[0] = acc[mt][nt][0]; d0[1] = acc[mt][nt][1];
            d1[0] = acc[mt][nt][2]; d1[1] = acc[mt][nt][3];
        }
    }
}

// ============================================================================
// hpart: fp16 hi/lo 3-term MMA.  g_hpb[b, m] = b1[m] + h0 @ W1[:,1024:]^T
// ============================================================================
__device__ __forceinline__ void hp_stage(int row0, int col0, int k0,
                                         uint32_t smb, int tid)
{
#pragma unroll
    for (int rep = 0; rep < 2; ++rep){
        int idx = tid + rep*256;
        int row = idx >> 2, c = idx & 3;
        uint32_t off = row*64 + ((uint32_t)(c ^ (row & 3)) << 4);
        size_t ea = (size_t)(row0 + row)*HDIM + k0 + c*8;
        size_t eb = (size_t)(col0 + row)*HDIM + k0 + c*8;
        cpasync16(smb +         off, g_h0h  + ea);
        cpasync16(smb +  8192 + off, g_h0l  + ea);
        cpasync16(smb + 16384 + off, g_w1kh + eb);
        cpasync16(smb + 24576 + off, g_w1kl + eb);
    }
}

__global__ __launch_bounds__(256,1) void hpart_mma(const float* __restrict__ b1)
{
    extern __shared__ char smem[];
    uint32_t smu = (uint32_t)__cvta_generic_to_shared(smem);
    const int tid = threadIdx.x, lane = tid & 31, wid = tid >> 5;
    const int warp_m = wid & 3, warp_n = wid >> 2;  // 4 x 2, warp tile 32x64
    const int row0 = blockIdx.x * 128, col0 = blockIdx.y * 128;

    float acc[2][8][4];
#pragma unroll
    for (int a = 0; a < 2; a++)
#pragma unroll
        for (int b = 0; b < 8; b++)
#pragma unroll
            for (int c = 0; c < 4; c++) acc[a][b][c] = 0.f;

    hp_stage(row0, col0, 0, smu, tid); cp_commit();
    const int nit = HDIM / 32;   // 16
    for (int it = 0; it < nit; ++it){
        if (it + 1 < nit){
            hp_stage(row0, col0, (it+1)*32, smu + ((it+1)&1)*GT_STAGE, tid);
            cp_commit();
            asm volatile("cp.async.wait_group 1;");
        } else {
            asm volatile("cp.async.wait_group 0;");
        }
        __syncthreads();
        uint32_t buf = smu + (it&1)*GT_STAGE;
#pragma unroll
        for (int s = 0; s < 2; ++s){
            uint32_t ah[2][4], al[2][4];
#pragma unroll
            for (int mt = 0; mt < 2; ++mt){
                int row = warp_m*32 + mt*16 + ((lane>>3)&1)*8 + (lane&7);
                int chunk = 2*s + (lane>>4);
                uint32_t addr = buf + row*64 + ((uint32_t)(chunk ^ (row&3)) << 4);
                ldsm4(ah[mt], addr);
                ldsm4(al[mt], addr + 8192);
            }
#pragma unroll
            for (int g = 0; g < 4; ++g){
                int nrow = warp_n*64 + g*16 + ((lane>>4)<<3) + (lane&7);
                int chunk = 2*s + ((lane>>3)&1);
                uint32_t baddr = buf + 16384 + nrow*64 + ((uint32_t)(chunk ^ (nrow&3)) << 4);
                uint32_t bh[4], bl[4];
                ldsm4(bh, baddr);
                ldsm4(bl, baddr + 8192);
#pragma unroll
                for (int mt = 0; mt < 2; ++mt){
                    mma16816h(acc[mt][2*g+0], ah[mt], bh+0);
                    mma16816h(acc[mt][2*g+0], ah[mt], bl+0);
                    mma16816h(acc[mt][2*g+0], al[mt], bh+0);
                    mma16816h(acc[mt][2*g+1], ah[mt], bh+2);
                    mma16816h(acc[mt][2*g+1], ah[mt], bl+2);
                    mma16816h(acc[mt][2*g+1], al[mt], bh+2);
                }
            }
        }
        __syncthreads();
    }

#pragma unroll
    for (int mt = 0; mt < 2; ++mt){
        int m = row0 + warp_m*32 + mt*16 + (lane>>2);
#pragma unroll
        for (int nt = 0; nt < 8; ++nt){
            int c = col0 + warp_n*64 + nt*8 + 2*(lane&3);
            float ba = b1[c], bb = b1[c+1];
            float* d0 = g_hpb + (size_t)m * H3 + c;
            float* d1 = g_hpb + (size_t)(m+8) * H3 + c;
            d0[0] = acc[mt][nt][0] + ba; d0[1] = acc[mt][nt][1] + bb;
            d1[0] = acc[mt][nt][2] + ba; d1[1] = acc[mt][nt][3] + bb;
        }
    }
}

// ============================================================================
// conv_enc (16 floats/thread) + merged weight conversion kernel
// ============================================================================
__global__ void conv_enc_kernel(const float* __restrict__ enc){
    size_t i = (size_t)blockIdx.x * 256 + threadIdx.x;    // group of 16 floats
    const float4* s = reinterpret_cast<const float4*>(enc) + i*4;
    uint4* d = reinterpret_cast<uint4*>(g_encf) + i*2;
    float4 s0 = s[0], s1 = s[1], s2 = s[2], s3 = s[3];
    d[0] = cvt8_f16(s0, s1);
    d[1] = cvt8_f16(s2, s3);
}

// merged: w1f | w1k hi/lo | ow | gw hi/lo | h0 hi/lo  (8 elems per thread)
#define CW_A 196608u                    /* w1f groups: 1536*128 */
#define CW_B (CW_A + 98304u)            /* w1k:  1536*64  */
#define CW_C (CW_B + 2048000u)          /* ow: 32000*64   */
#define CW_D (CW_C + 589824u)           /* gw: 2048*288   */
#define CW_E (CW_D + 16384u)            /* h0: 16384      */

__global__ void conv_weights(const float* __restrict__ W1,
                             const float* __restrict__ oW,
                             const float* __restrict__ Wih,
                             const float* __restrict__ Whh,
                             const float* __restrict__ hid)
{
    uint32_t i = blockIdx.x * 256 + threadIdx.x;
    if (i < CW_A){
        int row = i / 128, c8 = i % 128;
        const float4* s = reinterpret_cast<const float4*>(W1 + (size_t)row * H3 + c8 * 8);
        reinterpret_cast<uint4*>(g_w1f)[(size_t)row * 128 + c8] = cvt8_f16(s[0], s[1]);
    } else if (i < CW_B){
        uint32_t j = i - CW_A;
        int row = j / 64, c = j % 64;
        const float4* s = reinterpret_cast<const float4*>(W1 + (size_t)row * H3 + 1024 + c * 8);
        uint4 uh, ul; cvt8_hl(s[0], s[1], uh, ul);
        reinterpret_cast<uint4*>(g_w1kh)[(size_t)row * 64 + c] = uh;
        reinterpret_cast<uint4*>(g_w1kl)[(size_t)row * 64 + c] = ul;
    } else if (i < CW_C){
        uint32_t j = i - CW_B;
        const float4* s = reinterpret_cast<const float4*>(oW) + (size_t)j*2;
        reinterpret_cast<uint4*>(g_owf)[j] = cvt8_f16(s[0], s[1]);
    } else if (i < CW_D){
        uint32_t j = i - CW_C;
        int row = j / 288, c8 = j % 288;
        const float* src = (c8 < 224) ? (Wih + (size_t)row * 1792 + c8 * 8)
                                      : (Whh + (size_t)row * HDIM + (c8 - 224) * 8);
        const float4* s = reinterpret_cast<const float4*>(src);
        uint4 uh, ul; cvt8_hl(s[0], s[1], uh, ul);
        reinterpret_cast<uint4*>(g_gwh)[(size_t)row * 288 + c8] = uh;
        reinterpret_cast<uint4*>(g_gwl)[(size_t)row * 288 + c8] = ul;
    } else {
        uint32_t j = i - CW_D;
        const float4* s = reinterpret_cast<const float4*>(hid) + (size_t)j*2;
        uint4 uh, ul; cvt8_hl(s[0], s[1], uh, ul);
        reinterpret_cast<uint4*>(g_h0h)[j] = uh;
        reinterpret_cast<uint4*>(g_h0l)[j] = ul;
    }
}

// ============================================================================
// fused: softmax + context (fp16 enc) + fill x (fp16 hi/lo directly)
// ============================================================================
__global__ __launch_bounds__(256) void attn_finish(
    const float* __restrict__ b2, const int* __restrict__ ids,
    const float* __restrict__ emb, const float* __restrict__ hid)
{
    int b = blockIdx.x, t = threadIdx.x;
    __shared__ float att[128];
    __shared__ float red[128];

    if (t < 128){
        float sc = b2[0];
#pragma unroll
        for (int ct = 0; ct < NCTS; ct++)
            sc += g_scorep[(size_t)ct * ROWS + t * BATCH + b];
        att[t] = sc;
        red[t] = sc;
    }
    __syncthreads();
    for (int off = 64; off > 0; off >>= 1){
        if (t < off) red[t] = fmaxf(red[t], red[t+off]);
        __syncthreads();
    }
    float mx = red[0];
    __syncthreads();
    if (t < 128){
        float e = expf(att[t] - mx);
        att[t] = e;
        red[t] = e;
    }
    __syncthreads();
    for (int off = 64; off > 0; off >>= 1){
        if (t < off) red[t] += red[t+off];
        __syncthreads();
    }
    float inv = 1.0f / red[0];
    __syncthreads();
    if (t < 128) att[t] *= inv;
    __syncthreads();

    __half* xh = g_xh + (size_t)b * XDIM;
    __half* xl = g_xl + (size_t)b * XDIM;

    float a0=0.f, a1=0.f, a2=0.f, a3=0.f;
    const __half* ep = g_encf + (size_t)b * 1024 + 4*t;
    for (int s = 0; s < 128; s++){
        float a = att[s];
        uint2 raw = *reinterpret_cast<const uint2*>(ep + (size_t)s * BATCH * 1024);
        __half2 p0 = *reinterpret_cast<__half2*>(&raw.x);
        __half2 p1 = *reinterpret_cast<__half2*>(&raw.y);
        float2 f0 = __half22float2(p0), f1 = __half22float2(p1);
        a0 += a*f0.x; a1 += a*f0.y; a2 += a*f1.x; a3 += a*f1.y;
    }
    store4_hl(xh + EDIM + 4*t, xl + EDIM + 4*t, make_float4(a0, a1, a2, a3));

    if (t < 64){
        int id = ids[b];
        float4 ev = *reinterpret_cast<const float4*>(emb + (size_t)id * EDIM + 4*t);
        store4_hl(xh + 4*t, xl + 4*t, ev);
    }
    if (t < 128){
        float4 hv = *reinterpret_cast<const float4*>(hid + (size_t)b * HDIM + 4*t);
        store4_hl(xh + 1280 + 4*t, xl + 1280 + 4*t, hv);
        store4_hl(xh + 1792 + 4*t, xl + 1792 + 4*t, hv);
    }
}

// ============================================================================
// LSTM cell
// ============================================================================
__global__ void lstm_kernel(const float* __restrict__ bih, const float* __restrict__ bhh,
                            const float* __restrict__ cell, float* __restrict__ out)
{
    int b = blockIdx.x, j = threadIdx.x;
    float g4[4];
#pragma unroll
    for (int q = 0; q < 4; q++) {
        int c = q * HDIM + j;
        float v = bih[c] + bhh[c];
#pragma unroll
        for (int kc = 0; kc < NKC; kc++)
            v += g_gatesp[((size_t)kc * BATCH + b) * GDIM + c];
        g4[q] = v;
    }
    float ig = sigmf(g4[0]), fg = sigmf(g4[1]);
    float gg = tanhf(g4[2]), og = sigmf(g4[3]);
    float c0 = cell[(size_t)b * HDIM + j];
    float cn = fg * c0 + ig * gg;
    float hn = og * tanhf(cn);
    size_t hbase = (size_t)VOCAB * BATCH;
    out[hbase + (size_t)b * HDIM + j] = hn;
    out[hbase + (size_t)BATCH * HDIM + (size_t)b * HDIM + j] = cn;
    g_hf[b * HDIM + j] = __float2half_rn(hn);
}

// ============================================================================
extern "C" void kernel_launch(void* const* d_in, const int* in_sizes, int n_in,
                              void* d_out, int out_size)
{
    const int*   ids = (const int*)d_in[0];
    const float* enc = (const float*)d_in[1];
    const float* hid = (const float*)d_in[2];
    const float* cel = (const float*)d_in[3];
    const float* emb = (const float*)d_in[4];
    const float* Wih = (const float*)d_in[5];
    const float* Whh = (const float*)d_in[6];
    const float* bih = (const float*)d_in[7];
    const float* bhh = (const float*)d_in[8];
    const float* W1  = (const float*)d_in[9];
    const float* b1  = (const float*)d_in[10];
    const float* w2  = (const float*)d_in[11];
    const float* b2  = (const float*)d_in[12];
    const float* oW  = (const float*)d_in[13];
    const float* ob  = (const float*)d_in[14];
    float* out = (float*)d_out;

    cudaFuncSetAttribute(scorer_fp16, cudaFuncAttributeMaxDynamicSharedMemorySize, SC_SMEM);
    cudaFuncSetAttribute(logits_fp16, cudaFuncAttributeMaxDynamicSharedMemorySize, LG_SMEM);
    cudaFuncSetAttribute(gates_mma,   cudaFuncAttributeMaxDynamicSharedMemorySize, GT_SMEM);
    cudaFuncSetAttribute(hpart_mma,   cudaFuncAttributeMaxDynamicSharedMemorySize, GT_SMEM);

    conv_enc_kernel<<<(ROWS * KENC) / 4096, 256>>>(enc);
    conv_weights<<<CW_E / 256, 256>>>(W1, oW, Wih, Whh, hid);
    hpart_mma<<<dim3(BATCH / 128, H3 / 128), 256, GT_SMEM>>>(b1);

    scorer_fp16<<<dim3(NCTS, ROWS / 128), 256, SC_SMEM>>>(w2);
    attn_finish<<<BATCH, 256>>>(b2, ids, emb, hid);
    gates_mma<<<dim3(BATCH / 128, GDIM / 128, NKC), 256, GT_SMEM>>>();
    lstm_kernel<<<BATCH, 512>>>(bih, bhh, cel, out);
    logits_fp16<<<dim3(BATCH / 128, VOCAB / 256), 256, LG_SMEM>>>(ob, out);
}

// round 16
// speedup vs baseline: 1.0123x; 1.0123x over previous
#include <cuda_runtime.h>
#include <cuda_bf16.h>
#include <cuda_fp16.h>
#include <math.h>
#include <stdint.h>

#define S_LEN 128
#define BATCH 256
#define EDIM  256
#define HDIM  512
#define H3    1536
#define VOCAB 32000
#define ROWS  (S_LEN*BATCH)   /* 32768 */
#define XDIM  2304
#define GDIM  2048
#define NKC   6
#define NCTS  6               /* scorer col tiles of 256 */
#define KENC  1024

// ------------------------- device scratch ---------------------------------
__device__ __half g_encf[(size_t)ROWS*KENC];     // fp16 enc
__device__ __half g_w1f[H3*KENC];                // fp16 W1[:, :1024]
__device__ __half g_w1kh[H3*HDIM];               // W1[:, 1024:] hi
__device__ __half g_w1kl[H3*HDIM];               // W1[:, 1024:] lo
__device__ __half g_h0h[BATCH*HDIM];             // h0 hi
__device__ __half g_h0l[BATCH*HDIM];             // h0 lo
__device__ __half g_hf[BATCH*HDIM];              // fp16 h_new
__device__ __half g_gwh[(size_t)GDIM*XDIM];      // gates W hi (Wih|Whh concat)
__device__ __half g_gwl[(size_t)GDIM*XDIM];      // gates W lo
__device__ __half g_xh[BATCH*XDIM];              // x hi
__device__ __half g_xl[BATCH*XDIM];              // x lo
__device__ float g_hpb[BATCH*H3];          // b1 + h0 @ W1[:,1024:]^T  per (b,m)
__device__ float g_scorep[NCTS*ROWS];
__device__ float g_gatesp[NKC*BATCH*GDIM];

__device__ __forceinline__ float sigmf(float x){ return 1.0f/(1.0f+expf(-x)); }

// single-MUFU tanh (sm_75+ base ISA), max abs err ~4.9e-4
__device__ __forceinline__ float tanh_fast(float x){
    float y;
    asm("tanh.approx.f32 %0, %1;" : "=f"(y) : "f"(x));
    return y;
}

// ------------------------- mma.sync helpers -------------------------------
__device__ __forceinline__ void cpasync16(uint32_t dst, const void* src){
    asm volatile("cp.async.cg.shared.global [%0], [%1], 16;"
        :: "r"(dst), "l"(__cvta_generic_to_global(src)));
}
__device__ __forceinline__ void cp_commit(){ asm volatile("cp.async.commit_group;"); }

__device__ __forceinline__ void ldsm4(uint32_t* r, uint32_t addr){
    asm volatile("ldmatrix.sync.aligned.m8n8.x4.shared.b16 {%0,%1,%2,%3}, [%4];"
        : "=r"(r[0]), "=r"(r[1]), "=r"(r[2]), "=r"(r[3]) : "r"(addr));
}
__device__ __forceinline__ void mma16816h(float* d, const uint32_t* a, const uint32_t* b){
    asm volatile("mma.sync.aligned.m16n8k16.row.col.f32.f16.f16.f32 "
        "{%0,%1,%2,%3}, {%4,%5,%6,%7}, {%8,%9}, {%0,%1,%2,%3};"
        : "+f"(d[0]), "+f"(d[1]), "+f"(d[2]), "+f"(d[3])
        : "r"(a[0]), "r"(a[1]), "r"(a[2]), "r"(a[3]), "r"(b[0]), "r"(b[1]));
}

// 8-wide fp16 convert helpers (16B stores)
__device__ __forceinline__ uint4 cvt8_f16(float4 v0, float4 v1){
    __half h[8] = {__float2half_rn(v0.x), __float2half_rn(v0.y),
                   __float2half_rn(v0.z), __float2half_rn(v0.w),
                   __float2half_rn(v1.x), __float2half_rn(v1.y),
                   __float2half_rn(v1.z), __float2half_rn(v1.w)};
    return *reinterpret_cast<uint4*>(h);
}
__device__ __forceinline__ void cvt8_hl(float4 v0, float4 v1, uint4& uh, uint4& ul){
    float f[8] = {v0.x, v0.y, v0.z, v0.w, v1.x, v1.y, v1.z, v1.w};
    __half h[8], l[8];
#pragma unroll
    for (int q = 0; q < 8; q++){
        h[q] = __float2half_rn(f[q]);
        l[q] = __float2half_rn(f[q] - __half2float(h[q]));
    }
    uh = *reinterpret_cast<uint4*>(h);
    ul = *reinterpret_cast<uint4*>(l);
}
__device__ __forceinline__ void store4_hl(__half* dh, __half* dl, float4 v){
    float f[4] = {v.x, v.y, v.z, v.w};
    __half h[4], l[4];
#pragma unroll
    for (int q = 0; q < 4; q++){
        h[q] = __float2half_rn(f[q]);
        l[q] = __float2half_rn(f[q] - __half2float(h[q]));
    }
    *reinterpret_cast<uint2*>(dh) = *reinterpret_cast<uint2*>(h);
    *reinterpret_cast<uint2*>(dl) = *reinterpret_cast<uint2*>(l);
}

// ============================================================================
// Shared 64x64-warp-tile chunk compute (8 warps: 2 warp_m x 4 warp_n).
// A frags prefetched for both s-iters, B double-buffered. KC=32.
// A base = bufA (128 rows x 64B swizzled); B base = bufB (256 rows x 64B).
// ============================================================================
#define SC_STAGE 24576

__device__ __forceinline__ void sc_chunk2(uint32_t bufA, uint32_t bufB,
                                          int warp_m, int warp_n,
                                          int lane, float acc[4][8][4])
{
    uint32_t a[2][4][4];
#pragma unroll
    for (int s = 0; s < 2; ++s)
#pragma unroll
        for (int mt = 0; mt < 4; ++mt){
            int row = warp_m*64 + mt*16 + ((lane>>3)&1)*8 + (lane&7);
            int chunk = 2*s + (lane>>4);
            ldsm4(a[s][mt], bufA + row*64 + ((uint32_t)(chunk ^ (row&3)) << 4));
        }

    uint32_t b[2][4];
    {   // first B fragment (s=0, g=0)
        int nrow = warp_n*64 + 0*16 + ((lane>>4)<<3) + (lane&7);
        int chunk = 0 + ((lane>>3)&1);
        ldsm4(b[0], bufB + nrow*64 + ((uint32_t)(chunk ^ (nrow&3)) << 4));
    }
#pragma unroll
    for (int k = 0; k < 8; ++k){
        int s = k >> 2, g = k & 3;
        if (k < 7){
            int kn = k + 1, sn = kn >> 2, gn = kn & 3;
            int nrow = warp_n*64 + gn*16 + ((lane>>4)<<3) + (lane&7);
            int chunk = 2*sn + ((lane>>3)&1);
            ldsm4(b[(k+1)&1], bufB + nrow*64 + ((uint32_t)(chunk ^ (nrow&3)) << 4));
        }
        const uint32_t* bc = b[k&1];
#pragma unroll
        for (int mt = 0; mt < 4; ++mt){
            mma16816h(acc[mt][2*g+0], a[s][mt], bc+0);
            mma16816h(acc[mt][2*g+1], a[s][mt], bc+2);
        }
    }
}
__device__ __forceinline__ void sc_chunk(uint32_t buf, int warp_m, int warp_n,
                                         int lane, float acc[4][8][4])
{
    sc_chunk2(buf, buf + 8192, warp_m, warp_n, lane, acc);
}

// ============================================================================
// Scorer: fp16 MMA, 256 threads / 8 warps, CTA tile 128x256.
// R12 config: 6 smem stages, TWO chunks per loop iter (16 iters), wait 1.
// ============================================================================
#define SC_NSTG  6
#define SC_SMEM  (SC_NSTG*SC_STAGE)

__device__ __forceinline__ void sc_stage(int row0, int col0, int k0,
                                         uint32_t smb, int tid)
{
#pragma unroll
    for (int rep = 0; rep < 6; ++rep){
        int idx = tid + rep*256;
        if (idx < 512){
            int row = idx >> 2, c = idx & 3;
            uint32_t off = row*64 + ((uint32_t)(c ^ (row & 3)) << 4);
            cpasync16(smb + off, g_encf + (size_t)(row0 + row)*KENC + k0 + c*8);
        } else {
            int j = idx - 512;
            int row = j >> 2, c = j & 3;
            uint32_t off = 8192 + row*64 + ((uint32_t)(c ^ (row & 3)) << 4);
            cpasync16(smb + off, g_w1f + (size_t)(col0 + row)*KENC + k0 + c*8);
        }
    }
}

__global__ __launch_bounds__(256,1) void scorer_fp16(const float* __restrict__ w2)
{
    extern __shared__ char smem[];
    uint32_t smu = (uint32_t)__cvta_generic_to_shared(smem);
    const int tid = threadIdx.x, lane = tid & 31, wid = tid >> 5;
    const int warp_m = wid & 1, warp_n = wid >> 1;   // 2 x 4 warps, tile 64x64
    const int row0 = blockIdx.y * 128, col0 = blockIdx.x * 256;

    float acc[4][8][4];
#pragma unroll
    for (int a = 0; a < 4; a++)
#pragma unroll
        for (int b = 0; b < 8; b++)
#pragma unroll
            for (int c = 0; c < 4; c++) acc[a][b][c] = 0.f;

    // prologue: stage chunk pairs 0 and 1 (chunks 0..3)
    sc_stage(row0, col0,  0, smu + 0*SC_STAGE, tid);
    sc_stage(row0, col0, 32, smu + 1*SC_STAGE, tid);
    cp_commit();
    sc_stage(row0, col0, 64, smu + 2*SC_STAGE, tid);
    sc_stage(row0, col0, 96, smu + 3*SC_STAGE, tid);
    cp_commit();

    for (int p = 0; p < 16; ++p){
        asm volatile("cp.async.wait_group 1;");
        __syncthreads();
        sc_chunk(smu + ((2*p    ) % SC_NSTG)*SC_STAGE, warp_m, warp_n, lane, acc);
        sc_chunk(smu + ((2*p + 1) % SC_NSTG)*SC_STAGE, warp_m, warp_n, lane, acc);
        if (p + 2 < 16){
            int c0 = (2*p + 4), c1 = (2*p + 5);
            sc_stage(row0, col0, c0*32, smu + (c0 % SC_NSTG)*SC_STAGE, tid);
            sc_stage(row0, col0, c1*32, smu + (c1 % SC_NSTG)*SC_STAGE, tid);
        }
        cp_commit();   // empty group when no stage issued: keeps wait count exact
    }

    // epilogue: per-row w2-weighted tanh reduction over this CTA's 256 cols
    __syncthreads();
    float* sred = (float*)smem;
#pragma unroll
    for (int mt = 0; mt < 4; ++mt){
#pragma unroll
        for (int h = 0; h < 2; ++h){
            int row_local = warp_m*64 + mt*16 + h*8 + (lane>>2);
            int m0 = row0 + row_local;
            const float* hp = g_hpb + (size_t)(m0 & 255) * H3;
            float rs = 0.f;
#pragma unroll
            for (int nt = 0; nt < 8; ++nt){
                int nc = col0 + warp_n*64 + nt*8 + 2*(lane&3);
                rs += w2[nc]   * tanh_fast(acc[mt][nt][2*h+0] + hp[nc])
                    + w2[nc+1] * tanh_fast(acc[mt][nt][2*h+1] + hp[nc+1]);
            }
            rs += __shfl_xor_sync(0xffffffffu, rs, 1);
            rs += __shfl_xor_sync(0xffffffffu, rs, 2);
            if ((lane & 3) == 0) sred[warp_n*128 + row_local] = rs;
        }
    }
    __syncthreads();
    if (tid < 128)
        g_scorep[(size_t)blockIdx.x * ROWS + row0 + tid] =
            sred[tid] + sred[128 + tid] + sred[256 + tid] + sred[384 + tid];
}

// ============================================================================
// Logits with FUSED oW conversion: A = g_hf (fp16), B = out_W staged as fp32
// and converted warp-locally to fp16 each chunk.
// Ring: 4 slots x 40KB (A 8KB @0, B32 32KB @8192); B16 16KB @163840.
// 16 chunks, 1 chunk/iter, lookahead 3, wait_group 2.
// ============================================================================
#define LGS_SLOT 40960
#define LGS_B16  (4*LGS_SLOT)
#define LG_SMEM  (4*LGS_SLOT + 16384)

__device__ __forceinline__ void lg_stage(const float* __restrict__ oW,
                                         int row0, int col0, int k0,
                                         uint32_t slot, int tid)
{
#pragma unroll
    for (int rep = 0; rep < 10; ++rep){
        int idx = tid + rep*256;
        if (idx < 512){
            int row = idx >> 2, c = idx & 3;
            uint32_t off = row*64 + ((uint32_t)(c ^ (row & 3)) << 4);
            cpasync16(slot + off, g_hf + (size_t)(row0 + row)*HDIM + k0 + c*8);
        } else {
            int j = idx - 512;              // 0..2047
            int row = j >> 3, seg = j & 7;  // 256 rows x 8 x 16B, linear
            cpasync16(slot + 8192 + row*128 + seg*16,
                      oW + (size_t)(col0 + row)*HDIM + k0 + seg*4);
        }
    }
}

__global__ __launch_bounds__(256,1) void logits_fp16(const float* __restrict__ oW,
                                                     const float* __restrict__ ob,
                                                     float* __restrict__ out)
{
    extern __shared__ char smem[];
    uint32_t smu = (uint32_t)__cvta_generic_to_shared(smem);
    const int tid = threadIdx.x, lane = tid & 31, wid = tid >> 5;
    const int warp_m = wid & 1, warp_n = wid >> 1;   // 2 x 4 warps, tile 64x64
    const int row0 = blockIdx.x * 128, col0 = blockIdx.y * 256;

    float acc[4][8][4];
#pragma unroll
    for (int a = 0; a < 4; a++)
#pragma unroll
        for (int b = 0; b < 8; b++)
#pragma unroll
            for (int c = 0; c < 4; c++) acc[a][b][c] = 0.f;

    lg_stage(oW, row0, col0,  0, smu + 0*LGS_SLOT, tid); cp_commit();
    lg_stage(oW, row0, col0, 32, smu + 1*LGS_SLOT, tid); cp_commit();
    lg_stage(oW, row0, col0, 64, smu + 2*LGS_SLOT, tid); cp_commit();

    const uint32_t b16 = smu + LGS_B16;
    for (int c = 0; c < 16; ++c){
        asm volatile("cp.async.wait_group 2;");
        __syncthreads();
        uint32_t slot = smu + (c & 3)*LGS_SLOT;

        // warp-local convert: rows warp_n*64 .. +63 of B32 -> B16 (both warp_m
        // duplicates write identical values; benign)
        {
            const char* base = smem + (slot - smu) + 8192 + warp_n*64*128;
#pragma unroll
            for (int i = 0; i < 16; ++i){
                int row_local = (lane >> 3) + i*4;
                int seg = lane & 7;
                float4 v = *reinterpret_cast<const float4*>(base + row_local*128 + seg*16);
                __half hv[4] = {__float2half_rn(v.x), __float2half_rn(v.y),
                                __float2half_rn(v.z), __float2half_rn(v.w)};
                int nrow = warp_n*64 + row_local;
                int cc = seg >> 1, sub = (seg & 1)*8;
                *reinterpret_cast<uint2*>(smem + (b16 - smu) + nrow*64 +
                    ((uint32_t)(cc ^ (nrow&3)) << 4) + sub) = *reinterpret_cast<uint2*>(hv);
            }
        }
        __syncwarp();

        sc_chunk2(slot, b16, warp_m, warp_n, lane, acc);

        if (c + 3 < 16)
            lg_stage(oW, row0, col0, (c+3)*32, smu + ((c+3) & 3)*LGS_SLOT, tid);
        cp_commit();
    }

#pragma unroll
    for (int mt = 0; mt < 4; ++mt){
#pragma unroll
        for (int h = 0; h < 2; ++h){
            int m = row0 + warp_m*64 + mt*16 + h*8 + (lane>>2);
#pragma unroll
            for (int nt = 0; nt < 8; ++nt){
                int c = col0 + warp_n*64 + nt*8 + 2*(lane&3);
                float2 v = make_float2(acc[mt][nt][2*h+0] + ob[c],
                                       acc[mt][nt][2*h+1] + ob[c+1]);
                *(float2*)(out + (size_t)m * VOCAB + c) = v;
            }
        }
    }
}

// ============================================================================
// Gates: fp16 hi/lo 3-term MMA. CTA 128x128, split-K=6 (chunks of 384).
// ============================================================================
#define GT_STAGE 32768
#define GT_SMEM  (2*GT_STAGE)

__device__ __forceinline__ void gt_stage(int row0, int col0, int k0,
                                         uint32_t smb, int tid)
{
#pragma unroll
    for (int rep = 0; rep < 2; ++rep){
        int idx = tid + rep*256;
        int row = idx >> 2, c = idx & 3;
        uint32_t off = row*64 + ((uint32_t)(c ^ (row & 3)) << 4);
        size_t ea = (size_t)(row0 + row)*XDIM + k0 + c*8;
        size_t eb = (size_t)(col0 + row)*XDIM + k0 + c*8;
        cpasync16(smb +         off, g_xh  + ea);
        cpasync16(smb +  8192 + off, g_xl  + ea);
        cpasync16(smb + 16384 + off, g_gwh + eb);
        cpasync16(smb + 24576 + off, g_gwl + eb);
    }
}

__global__ __launch_bounds__(256,1) void gates_mma()
{
    extern __shared__ char smem[];
    uint32_t smu = (uint32_t)__cvta_generic_to_shared(smem);
    const int tid = threadIdx.x, lane = tid & 31, wid = tid >> 5;
    const int warp_m = wid & 3, warp_n = wid >> 2;  // 4 x 2, warp tile 32x64
    const int row0 = blockIdx.x * 128, col0 = blockIdx.y * 128;
    const int kbeg = blockIdx.z * (XDIM / NKC);     // 384 per chunk

    float acc[2][8][4];
#pragma unroll
    for (int a = 0; a < 2; a++)
#pragma unroll
        for (int b = 0; b < 8; b++)
#pragma unroll
            for (int c = 0; c < 4; c++) acc[a][b][c] = 0.f;

    gt_stage(row0, col0, kbeg, smu, tid); cp_commit();
    const int nit = (XDIM / NKC) / 32;   // 12
    for (int it = 0; it < nit; ++it){
        if (it + 1 < nit){
            gt_stage(row0, col0, kbeg + (it+1)*32, smu + ((it+1)&1)*GT_STAGE, tid);
            cp_commit();
            asm volatile("cp.async.wait_group 1;");
        } else {
            asm volatile("cp.async.wait_group 0;");
        }
        __syncthreads();
        uint32_t buf = smu + (it&1)*GT_STAGE;
#pragma unroll
        for (int s = 0; s < 2; ++s){
            uint32_t ah[2][4], al[2][4];
#pragma unroll
            for (int mt = 0; mt < 2; ++mt){
                int row = warp_m*32 + mt*16 + ((lane>>3)&1)*8 + (lane&7);
                int chunk = 2*s + (lane>>4);
                uint32_t addr = buf + row*64 + ((uint32_t)(chunk ^ (row&3)) << 4);
                ldsm4(ah[mt], addr);
                ldsm4(al[mt], addr + 8192);
            }
#pragma unroll
            for (int g = 0; g < 4; ++g){
                int nrow = warp_n*64 + g*16 + ((lane>>4)<<3) + (lane&7);
                int chunk = 2*s + ((lane>>3)&1);
                uint32_t baddr = buf + 16384 + nrow*64 + ((uint32_t)(chunk ^ (nrow&3)) << 4);
                uint32_t bh[4], bl[4];
                ldsm4(bh, baddr);
                ldsm4(bl, baddr + 8192);
#pragma unroll
                for (int mt = 0; mt < 2; ++mt){
                    mma16816h(acc[mt][2*g+0], ah[mt], bh+0);
                    mma16816h(acc[mt][2*g+0], ah[mt], bl+0);
                    mma16816h(acc[mt][2*g+0], al[mt], bh+0);
                    mma16816h(acc[mt][2*g+1], ah[mt], bh+2);
                    mma16816h(acc[mt][2*g+1], ah[mt], bl+2);
                    mma16816h(acc[mt][2*g+1], al[mt], bh+2);
                }
            }
        }
        __syncthreads();
    }

#pragma unroll
    for (int mt = 0; mt < 2; ++mt){
        int m = row0 + warp_m*32 + mt*16 + (lane>>2);
#pragma unroll
        for (int nt = 0; nt < 8; ++nt){
            int c = col0 + warp_n*64 + nt*8 + 2*(lane&3);
            float* d0 = g_gatesp + ((size_t)blockIdx.z * BATCH + m) * GDIM + c;
            float* d1 = g_gatesp + ((size_t)blockIdx.z * BATCH + m + 8) * GDIM + c;
            d0[0] = acc[mt][nt][0]; d0[1] = acc[mt][nt][1];
            d1[0] = acc[mt][nt][2]; d1[1] = acc[mt][nt][3];
        }
    }
}

// ============================================================================
// hpart: fp16 hi/lo 3-term MMA.  g_hpb[b, m] = b1[m] + h0 @ W1[:,1024:]^T
// ============================================================================
__device__ __forceinline__ void hp_stage(int row0, int col0, int k0,
                                         uint32_t smb, int tid)
{
#pragma unroll
    for (int rep = 0; rep < 2; ++rep){
        int idx = tid + rep*256;
        int row = idx >> 2, c = idx & 3;
        uint32_t off = row*64 + ((uint32_t)(c ^ (row & 3)) << 4);
        size_t ea = (size_t)(row0 + row)*HDIM + k0 + c*8;
        size_t eb = (size_t)(col0 + row)*HDIM + k0 + c*8;
        cpasync16(smb +         off, g_h0h  + ea);
        cpasync16(smb +  8192 + off, g_h0l  + ea);
        cpasync16(smb + 16384 + off, g_w1kh + eb);
        cpasync16(smb + 24576 + off, g_w1kl + eb);
    }
}

__global__ __launch_bounds__(256,1) void hpart_mma(const float* __restrict__ b1)
{
    extern __shared__ char smem[];
    uint32_t smu = (uint32_t)__cvta_generic_to_shared(smem);
    const int tid = threadIdx.x, lane = tid & 31, wid = tid >> 5;
    const int warp_m = wid & 3, warp_n = wid >> 2;  // 4 x 2, warp tile 32x64
    const int row0 = blockIdx.x * 128, col0 = blockIdx.y * 128;

    float acc[2][8][4];
#pragma unroll
    for (int a = 0; a < 2; a++)
#pragma unroll
        for (int b = 0; b < 8; b++)
#pragma unroll
            for (int c = 0; c < 4; c++) acc[a][b][c] = 0.f;

    hp_stage(row0, col0, 0, smu, tid); cp_commit();
    const int nit = HDIM / 32;   // 16
    for (int it = 0; it < nit; ++it){
        if (it + 1 < nit){
            hp_stage(row0, col0, (it+1)*32, smu + ((it+1)&1)*GT_STAGE, tid);
            cp_commit();
            asm volatile("cp.async.wait_group 1;");
        } else {
            asm volatile("cp.async.wait_group 0;");
        }
        __syncthreads();
        uint32_t buf = smu + (it&1)*GT_STAGE;
#pragma unroll
        for (int s = 0; s < 2; ++s){
            uint32_t ah[2][4], al[2][4];
#pragma unroll
            for (int mt = 0; mt < 2; ++mt){
                int row = warp_m*32 + mt*16 + ((lane>>3)&1)*8 + (lane&7);
                int chunk = 2*s + (lane>>4);
                uint32_t addr = buf + row*64 + ((uint32_t)(chunk ^ (row&3)) << 4);
                ldsm4(ah[mt], addr);
                ldsm4(al[mt], addr + 8192);
            }
#pragma unroll
            for (int g = 0; g < 4; ++g){
                int nrow = warp_n*64 + g*16 + ((lane>>4)<<3) + (lane&7);
                int chunk = 2*s + ((lane>>3)&1);
                uint32_t baddr = buf + 16384 + nrow*64 + ((uint32_t)(chunk ^ (nrow&3)) << 4);
                uint32_t bh[4], bl[4];
                ldsm4(bh, baddr);
                ldsm4(bl, baddr + 8192);
#pragma unroll
                for (int mt = 0; mt < 2; ++mt){
                    mma16816h(acc[mt][2*g+0], ah[mt], bh+0);
                    mma16816h(acc[mt][2*g+0], ah[mt], bl+0);
                    mma16816h(acc[mt][2*g+0], al[mt], bh+0);
                    mma16816h(acc[mt][2*g+1], ah[mt], bh+2);
                    mma16816h(acc[mt][2*g+1], ah[mt], bl+2);
                    mma16816h(acc[mt][2*g+1], al[mt], bh+2);
                }
            }
        }
        __syncthreads();
    }

#pragma unroll
    for (int mt = 0; mt < 2; ++mt){
        int m = row0 + warp_m*32 + mt*16 + (lane>>2);
#pragma unroll
        for (int nt = 0; nt < 8; ++nt){
            int c = col0 + warp_n*64 + nt*8 + 2*(lane&3);
            float ba = b1[c], bb = b1[c+1];
            float* d0 = g_hpb + (size_t)m * H3 + c;
            float* d1 = g_hpb + (size_t)(m+8) * H3 + c;
            d0[0] = acc[mt][nt][0] + ba; d0[1] = acc[mt][nt][1] + bb;
            d1[0] = acc[mt][nt][2] + ba; d1[1] = acc[mt][nt][3] + bb;
        }
    }
}

// ============================================================================
// conv_enc (16 floats/thread) + merged weight conversion (no oW anymore)
// ============================================================================
__global__ void conv_enc_kernel(const float* __restrict__ enc){
    size_t i = (size_t)blockIdx.x * 256 + threadIdx.x;    // group of 16 floats
    const float4* s = reinterpret_cast<const float4*>(enc) + i*4;
    uint4* d = reinterpret_cast<uint4*>(g_encf) + i*2;
    float4 s0 = s[0], s1 = s[1], s2 = s[2], s3 = s[3];
    d[0] = cvt8_f16(s0, s1);
    d[1] = cvt8_f16(s2, s3);
}

// merged: w1f | w1k hi/lo | gw hi/lo | h0 hi/lo  (8 elems per thread)
#define CW_A 196608u                    /* w1f groups: 1536*128 */
#define CW_B (CW_A + 98304u)            /* w1k:  1536*64  */
#define CW_D (CW_B + 589824u)           /* gw: 2048*288   */
#define CW_E (CW_D + 16384u)            /* h0: 16384      */

__global__ void conv_weights(const float* __restrict__ W1,
                             const float* __restrict__ Wih,
                             const float* __restrict__ Whh,
                             const float* __restrict__ hid)
{
    uint32_t i = blockIdx.x * 256 + threadIdx.x;
    if (i < CW_A){
        int row = i / 128, c8 = i % 128;
        const float4* s = reinterpret_cast<const float4*>(W1 + (size_t)row * H3 + c8 * 8);
        reinterpret_cast<uint4*>(g_w1f)[(size_t)row * 128 + c8] = cvt8_f16(s[0], s[1]);
    } else if (i < CW_B){
        uint32_t j = i - CW_A;
        int row = j / 64, c = j % 64;
        const float4* s = reinterpret_cast<const float4*>(W1 + (size_t)row * H3 + 1024 + c * 8);
        uint4 uh, ul; cvt8_hl(s[0], s[1], uh, ul);
        reinterpret_cast<uint4*>(g_w1kh)[(size_t)row * 64 + c] = uh;
        reinterpret_cast<uint4*>(g_w1kl)[(size_t)row * 64 + c] = ul;
    } else if (i < CW_D){
        uint32_t j = i - CW_B;
        int row = j / 288, c8 = j % 288;
        const float* src = (c8 < 224) ? (Wih + (size_t)row * 1792 + c8 * 8)
                                      : (Whh + (size_t)row * HDIM + (c8 - 224) * 8);
        const float4* s = reinterpret_cast<const float4*>(src);
        uint4 uh, ul; cvt8_hl(s[0], s[1], uh, ul);
        reinterpret_cast<uint4*>(g_gwh)[(size_t)row * 288 + c8] = uh;
        reinterpret_cast<uint4*>(g_gwl)[(size_t)row * 288 + c8] = ul;
    } else {
        uint32_t j = i - CW_D;
        const float4* s = reinterpret_cast<const float4*>(hid) + (size_t)j*2;
        uint4 uh, ul; cvt8_hl(s[0], s[1], uh, ul);
        reinterpret_cast<uint4*>(g_h0h)[j] = uh;
        reinterpret_cast<uint4*>(g_h0l)[j] = ul;
    }
}

// ============================================================================
// fused: softmax + context (fp16 enc) + fill x (fp16 hi/lo directly)
// ============================================================================
__global__ __launch_bounds__(256) void attn_finish(
    const float* __restrict__ b2, const int* __restrict__ ids,
    const float* __restrict__ emb, const float* __restrict__ hid)
{
    int b = blockIdx.x, t = threadIdx.x;
    __shared__ float att[128];
    __shared__ float red[128];

    if (t < 128){
        float sc = b2[0];
#pragma unroll
        for (int ct = 0; ct < NCTS; ct++)
            sc += g_scorep[(size_t)ct * ROWS + t * BATCH + b];
        att[t] = sc;
        red[t] = sc;
    }
    __syncthreads();
    for (int off = 64; off > 0; off >>= 1){
        if (t < off) red[t] = fmaxf(red[t], red[t+off]);
        __syncthreads();
    }
    float mx = red[0];
    __syncthreads();
    if (t < 128){
        float e = expf(att[t] - mx);
        att[t] = e;
        red[t] = e;
    }
    __syncthreads();
    for (int off = 64; off > 0; off >>= 1){
        if (t < off) red[t] += red[t+off];
        __syncthreads();
    }
    float inv = 1.0f / red[0];
    __syncthreads();
    if (t < 128) att[t] *= inv;
    __syncthreads();

    __half* xh = g_xh + (size_t)b * XDIM;
    __half* xl = g_xl + (size_t)b * XDIM;

    float a0=0.f, a1=0.f, a2=0.f, a3=0.f;
    const __half* ep = g_encf + (size_t)b * 1024 + 4*t;
    for (int s = 0; s < 128; s++){
        float a = att[s];
        uint2 raw = *reinterpret_cast<const uint2*>(ep + (size_t)s * BATCH * 1024);
        __half2 p0 = *reinterpret_cast<__half2*>(&raw.x);
        __half2 p1 = *reinterpret_cast<__half2*>(&raw.y);
        float2 f0 = __half22float2(p0), f1 = __half22float2(p1);
        a0 += a*f0.x; a1 += a*f0.y; a2 += a*f1.x; a3 += a*f1.y;
    }
    store4_hl(xh + EDIM + 4*t, xl + EDIM + 4*t, make_float4(a0, a1, a2, a3));

    if (t < 64){
        int id = ids[b];
        float4 ev = *reinterpret_cast<const float4*>(emb + (size_t)id * EDIM + 4*t);
        store4_hl(xh + 4*t, xl + 4*t, ev);
    }
    if (t < 128){
        float4 hv = *reinterpret_cast<const float4*>(hid + (size_t)b * HDIM + 4*t);
        store4_hl(xh + 1280 + 4*t, xl + 1280 + 4*t, hv);
        store4_hl(xh + 1792 + 4*t, xl + 1792 + 4*t, hv);
    }
}

// ============================================================================
// LSTM cell
// ============================================================================
__global__ void lstm_kernel(const float* __restrict__ bih, const float* __restrict__ bhh,
                            const float* __restrict__ cell, float* __restrict__ out)
{
    int b = blockIdx.x, j = threadIdx.x;
    float g4[4];
#pragma unroll
    for (int q = 0; q < 4; q++) {
        int c = q * HDIM + j;
        float v = bih[c] + bhh[c];
#pragma unroll
        for (int kc = 0; kc < NKC; kc++)
            v += g_gatesp[((size_t)kc * BATCH + b) * GDIM + c];
        g4[q] = v;
    }
    float ig = sigmf(g4[0]), fg = sigmf(g4[1]);
    float gg = tanhf(g4[2]), og = sigmf(g4[3]);
    float c0 = cell[(size_t)b * HDIM + j];
    float cn = fg * c0 + ig * gg;
    float hn = og * tanhf(cn);
    size_t hbase = (size_t)VOCAB * BATCH;
    out[hbase + (size_t)b * HDIM + j] = hn;
    out[hbase + (size_t)BATCH * HDIM + (size_t)b * HDIM + j] = cn;
    g_hf[b * HDIM + j] = __float2half_rn(hn);
}

// ============================================================================
extern "C" void kernel_launch(void* const* d_in, const int* in_sizes, int n_in,
                              void* d_out, int out_size)
{
    const int*   ids = (const int*)d_in[0];
    const float* enc = (const float*)d_in[1];
    const float* hid = (const float*)d_in[2];
    const float* cel = (const float*)d_in[3];
    const float* emb = (const float*)d_in[4];
    const float* Wih = (const float*)d_in[5];
    const float* Whh = (const float*)d_in[6];
    const float* bih = (const float*)d_in[7];
    const float* bhh = (const float*)d_in[8];
    const float* W1  = (const float*)d_in[9];
    const float* b1  = (const float*)d_in[10];
    const float* w2  = (const float*)d_in[11];
    const float* b2  = (const float*)d_in[12];
    const float* oW  = (const float*)d_in[13];
    const float* ob  = (const float*)d_in[14];
    float* out = (float*)d_out;

    cudaFuncSetAttribute(scorer_fp16, cudaFuncAttributeMaxDynamicSharedMemorySize, SC_SMEM);
    cudaFuncSetAttribute(logits_fp16, cudaFuncAttributeMaxDynamicSharedMemorySize, LG_SMEM);
    cudaFuncSetAttribute(gates_mma,   cudaFuncAttributeMaxDynamicSharedMemorySize, GT_SMEM);
    cudaFuncSetAttribute(hpart_mma,   cudaFuncAttributeMaxDynamicSharedMemorySize, GT_SMEM);

    conv_enc_kernel<<<(ROWS * KENC) / 4096, 256>>>(enc);
    conv_weights<<<CW_E / 256, 256>>>(W1, Wih, Whh, hid);
    hpart_mma<<<dim3(BATCH / 128, H3 / 128), 256, GT_SMEM>>>(b1);

    scorer_fp16<<<dim3(NCTS, ROWS / 128), 256, SC_SMEM>>>(w2);
    attn_finish<<<BATCH, 256>>>(b2, ids, emb, hid);
    gates_mma<<<dim3(BATCH / 128, GDIM / 128, NKC), 256, GT_SMEM>>>();
    lstm_kernel<<<BATCH, 512>>>(bih, bhh, cel, out);
    logits_fp16<<<dim3(BATCH / 128, VOCAB / 256), 256, LG_SMEM>>>(oW, ob, out);
}

// round 17
// speedup vs baseline: 1.1187x; 1.1051x over previous
#include <cuda_runtime.h>
#include <cuda_bf16.h>
#include <cuda_fp16.h>
#include <math.h>
#include <stdint.h>

#define S_LEN 128
#define BATCH 256
#define EDIM  256
#define HDIM  512
#define H3    1536
#define VOCAB 32000
#define ROWS  (S_LEN*BATCH)   /* 32768 */
#define XDIM  2304
#define GDIM  2048
#define NKC   6
#define NCTS  12              /* scorer col tiles of 128 */
#define KENC  1024

// ------------------------- device scratch ---------------------------------
__device__ __half g_encf[(size_t)ROWS*KENC];     // fp16 enc
__device__ __half g_w1f[H3*KENC];                // fp16 W1[:, :1024]
__device__ __half g_w1kh[H3*HDIM];               // W1[:, 1024:] hi
__device__ __half g_w1kl[H3*HDIM];               // W1[:, 1024:] lo
__device__ __half g_h0h[BATCH*HDIM];             // h0 hi
__device__ __half g_h0l[BATCH*HDIM];             // h0 lo
__device__ __half g_hf[BATCH*HDIM];              // fp16 h_new
__device__ __half g_gwh[(size_t)GDIM*XDIM];      // gates W hi (Wih|Whh concat)
__device__ __half g_gwl[(size_t)GDIM*XDIM];      // gates W lo
__device__ __half g_xh[BATCH*XDIM];              // x hi
__device__ __half g_xl[BATCH*XDIM];              // x lo
__device__ float g_hpb[BATCH*H3];          // b1 + h0 @ W1[:,1024:]^T  per (b,m)
__device__ float g_scorep[NCTS*ROWS];
__device__ float g_gatesp[NKC*BATCH*GDIM];

__device__ __forceinline__ float sigmf(float x){ return 1.0f/(1.0f+expf(-x)); }

// single-MUFU tanh (sm_75+ base ISA), max abs err ~4.9e-4
__device__ __forceinline__ float tanh_fast(float x){
    float y;
    asm("tanh.approx.f32 %0, %1;" : "=f"(y) : "f"(x));
    return y;
}

// ------------------------- mma.sync helpers -------------------------------
__device__ __forceinline__ void cpasync16(uint32_t dst, const void* src){
    asm volatile("cp.async.cg.shared.global [%0], [%1], 16;"
        :: "r"(dst), "l"(__cvta_generic_to_global(src)));
}
__device__ __forceinline__ void cp_commit(){ asm volatile("cp.async.commit_group;"); }

__device__ __forceinline__ void ldsm4(uint32_t* r, uint32_t addr){
    asm volatile("ldmatrix.sync.aligned.m8n8.x4.shared.b16 {%0,%1,%2,%3}, [%4];"
        : "=r"(r[0]), "=r"(r[1]), "=r"(r[2]), "=r"(r[3]) : "r"(addr));
}
__device__ __forceinline__ void mma16816h(float* d, const uint32_t* a, const uint32_t* b){
    asm volatile("mma.sync.aligned.m16n8k16.row.col.f32.f16.f16.f32 "
        "{%0,%1,%2,%3}, {%4,%5,%6,%7}, {%8,%9}, {%0,%1,%2,%3};"
        : "+f"(d[0]), "+f"(d[1]), "+f"(d[2]), "+f"(d[3])
        : "r"(a[0]), "r"(a[1]), "r"(a[2]), "r"(a[3]), "r"(b[0]), "r"(b[1]));
}

// 8-wide fp16 convert helpers (16B stores)
__device__ __forceinline__ uint4 cvt8_f16(float4 v0, float4 v1){
    __half h[8] = {__float2half_rn(v0.x), __float2half_rn(v0.y),
                   __float2half_rn(v0.z), __float2half_rn(v0.w),
                   __float2half_rn(v1.x), __float2half_rn(v1.y),
                   __float2half_rn(v1.z), __float2half_rn(v1.w)};
    return *reinterpret_cast<uint4*>(h);
}
__device__ __forceinline__ void cvt8_hl(float4 v0, float4 v1, uint4& uh, uint4& ul){
    float f[8] = {v0.x, v0.y, v0.z, v0.w, v1.x, v1.y, v1.z, v1.w};
    __half h[8], l[8];
#pragma unroll
    for (int q = 0; q < 8; q++){
        h[q] = __float2half_rn(f[q]);
        l[q] = __float2half_rn(f[q] - __half2float(h[q]));
    }
    uh = *reinterpret_cast<uint4*>(h);
    ul = *reinterpret_cast<uint4*>(l);
}
__device__ __forceinline__ void store4_hl(__half* dh, __half* dl, float4 v){
    float f[4] = {v.x, v.y, v.z, v.w};
    __half h[4], l[4];
#pragma unroll
    for (int q = 0; q < 4; q++){
        h[q] = __float2half_rn(f[q]);
        l[q] = __float2half_rn(f[q] - __half2float(h[q]));
    }
    *reinterpret_cast<uint2*>(dh) = *reinterpret_cast<uint2*>(h);
    *reinterpret_cast<uint2*>(dl) = *reinterpret_cast<uint2*>(l);
}

// ============================================================================
// Shared 64x64-warp-tile chunk compute. A frags prefetched for both s-iters,
// B double-buffered. KC=32. bufA: M rows x 64B swizzled; bufB: N rows x 64B.
// Valid for any warp_m/warp_n grid covering the CTA tile.
// ============================================================================
#define SC_STAGE 24576

__device__ __forceinline__ void sc_chunk2(uint32_t bufA, uint32_t bufB,
                                          int warp_m, int warp_n,
                                          int lane, float acc[4][8][4])
{
    uint32_t a[2][4][4];
#pragma unroll
    for (int s = 0; s < 2; ++s)
#pragma unroll
        for (int mt = 0; mt < 4; ++mt){
            int row = warp_m*64 + mt*16 + ((lane>>3)&1)*8 + (lane&7);
            int chunk = 2*s + (lane>>4);
            ldsm4(a[s][mt], bufA + row*64 + ((uint32_t)(chunk ^ (row&3)) << 4));
        }

    uint32_t b[2][4];
    {   // first B fragment (s=0, g=0)
        int nrow = warp_n*64 + 0*16 + ((lane>>4)<<3) + (lane&7);
        int chunk = 0 + ((lane>>3)&1);
        ldsm4(b[0], bufB + nrow*64 + ((uint32_t)(chunk ^ (nrow&3)) << 4));
    }
#pragma unroll
    for (int k = 0; k < 8; ++k){
        int s = k >> 2, g = k & 3;
        if (k < 7){
            int kn = k + 1, sn = kn >> 2, gn = kn & 3;
            int nrow = warp_n*64 + gn*16 + ((lane>>4)<<3) + (lane&7);
            int chunk = 2*sn + ((lane>>3)&1);
            ldsm4(b[(k+1)&1], bufB + nrow*64 + ((uint32_t)(chunk ^ (nrow&3)) << 4));
        }
        const uint32_t* bc = b[k&1];
#pragma unroll
        for (int mt = 0; mt < 4; ++mt){
            mma16816h(acc[mt][2*g+0], a[s][mt], bc+0);
            mma16816h(acc[mt][2*g+1], a[s][mt], bc+2);
        }
    }
}

// ============================================================================
// Scorer: fp16 MMA, 128 threads / 4 warps (2 warp_m x 2 warp_n, tile 64x64),
// CTA tile 128(M) x 128(N), TWO CTAs per SM. 6-stage ring of 16KB stages,
// TWO chunks per loop iter (16 iters), wait 1 (R12-verified schedule).
// ============================================================================
#define SC2_STAGE 16384
#define SC2_NSTG  6
#define SC2_SMEM  (SC2_NSTG*SC2_STAGE)   /* 96 KB */

__device__ __forceinline__ void sc_stage(int row0, int col0, int k0,
                                         uint32_t smb, int tid)
{
#pragma unroll
    for (int rep = 0; rep < 8; ++rep){
        int idx = tid + rep*128;
        if (idx < 512){
            int row = idx >> 2, c = idx & 3;
            uint32_t off = row*64 + ((uint32_t)(c ^ (row & 3)) << 4);
            cpasync16(smb + off, g_encf + (size_t)(row0 + row)*KENC + k0 + c*8);
        } else {
            int j = idx - 512;
            int row = j >> 2, c = j & 3;
            uint32_t off = 8192 + row*64 + ((uint32_t)(c ^ (row & 3)) << 4);
            cpasync16(smb + off, g_w1f + (size_t)(col0 + row)*KENC + k0 + c*8);
        }
    }
}

__global__ __launch_bounds__(128,2) void scorer_fp16(const float* __restrict__ w2)
{
    extern __shared__ char smem[];
    uint32_t smu = (uint32_t)__cvta_generic_to_shared(smem);
    const int tid = threadIdx.x, lane = tid & 31, wid = tid >> 5;
    const int warp_m = wid & 1, warp_n = wid >> 1;   // 2 x 2 warps, tile 64x64
    const int row0 = blockIdx.y * 128, col0 = blockIdx.x * 128;

    float acc[4][8][4];
#pragma unroll
    for (int a = 0; a < 4; a++)
#pragma unroll
        for (int b = 0; b < 8; b++)
#pragma unroll
            for (int c = 0; c < 4; c++) acc[a][b][c] = 0.f;

    // prologue: stage chunk pairs 0 and 1 (chunks 0..3)
    sc_stage(row0, col0,  0, smu + 0*SC2_STAGE, tid);
    sc_stage(row0, col0, 32, smu + 1*SC2_STAGE, tid);
    cp_commit();
    sc_stage(row0, col0, 64, smu + 2*SC2_STAGE, tid);
    sc_stage(row0, col0, 96, smu + 3*SC2_STAGE, tid);
    cp_commit();

    for (int p = 0; p < 16; ++p){
        asm volatile("cp.async.wait_group 1;");
        __syncthreads();
        uint32_t s0 = smu + ((2*p    ) % SC2_NSTG)*SC2_STAGE;
        uint32_t s1 = smu + ((2*p + 1) % SC2_NSTG)*SC2_STAGE;
        sc_chunk2(s0, s0 + 8192, warp_m, warp_n, lane, acc);
        sc_chunk2(s1, s1 + 8192, warp_m, warp_n, lane, acc);
        if (p + 2 < 16){
            int c0 = (2*p + 4), c1 = (2*p + 5);
            sc_stage(row0, col0, c0*32, smu + (c0 % SC2_NSTG)*SC2_STAGE, tid);
            sc_stage(row0, col0, c1*32, smu + (c1 % SC2_NSTG)*SC2_STAGE, tid);
        }
        cp_commit();   // empty group when no stage issued: keeps wait count exact
    }

    // epilogue: per-row w2-weighted tanh reduction over this CTA's 128 cols
    __syncthreads();
    float* sred = (float*)smem;
#pragma unroll
    for (int mt = 0; mt < 4; ++mt){
#pragma unroll
        for (int h = 0; h < 2; ++h){
            int row_local = warp_m*64 + mt*16 + h*8 + (lane>>2);
            int m0 = row0 + row_local;
            const float* hp = g_hpb + (size_t)(m0 & 255) * H3;
            float rs = 0.f;
#pragma unroll
            for (int nt = 0; nt < 8; ++nt){
                int nc = col0 + warp_n*64 + nt*8 + 2*(lane&3);
                rs += w2[nc]   * tanh_fast(acc[mt][nt][2*h+0] + hp[nc])
                    + w2[nc+1] * tanh_fast(acc[mt][nt][2*h+1] + hp[nc+1]);
            }
            rs += __shfl_xor_sync(0xffffffffu, rs, 1);
            rs += __shfl_xor_sync(0xffffffffu, rs, 2);
            if ((lane & 3) == 0) sred[warp_n*128 + row_local] = rs;
        }
    }
    __syncthreads();
    g_scorep[(size_t)blockIdx.x * ROWS + row0 + tid] =
        sred[tid] + sred[128 + tid];
}

// ============================================================================
// Logits with FUSED oW conversion (verified R16): A = g_hf fp16, B = out_W
// staged fp32, converted warp-locally. 256 threads, 2x4 warps, CTA 128x256.
// Ring: 4 slots x 40KB; B16 16KB. 16 chunks, lookahead 3, wait 2.
// ============================================================================
#define LGS_SLOT 40960
#define LGS_B16  (4*LGS_SLOT)
#define LG_SMEM  (4*LGS_SLOT + 16384)

__device__ __forceinline__ void lg_stage(const float* __restrict__ oW,
                                         int row0, int col0, int k0,
                                         uint32_t slot, int tid)
{
#pragma unroll
    for (int rep = 0; rep < 10; ++rep){
        int idx = tid + rep*256;
        if (idx < 512){
            int row = idx >> 2, c = idx & 3;
            uint32_t off = row*64 + ((uint32_t)(c ^ (row & 3)) << 4);
            cpasync16(slot + off, g_hf + (size_t)(row0 + row)*HDIM + k0 + c*8);
        } else {
            int j = idx - 512;              // 0..2047
            int row = j >> 3, seg = j & 7;  // 256 rows x 8 x 16B, linear
            cpasync16(slot + 8192 + row*128 + seg*16,
                      oW + (size_t)(col0 + row)*HDIM + k0 + seg*4);
        }
    }
}

__global__ __launch_bounds__(256,1) void logits_fp16(const float* __restrict__ oW,
                                                     const float* __restrict__ ob,
                                                     float* __restrict__ out)
{
    extern __shared__ char smem[];
    uint32_t smu = (uint32_t)__cvta_generic_to_shared(smem);
    const int tid = threadIdx.x, lane = tid & 31, wid = tid >> 5;
    const int warp_m = wid & 1, warp_n = wid >> 1;   // 2 x 4 warps, tile 64x64
    const int row0 = blockIdx.x * 128, col0 = blockIdx.y * 256;

    float acc[4][8][4];
#pragma unroll
    for (int a = 0; a < 4; a++)
#pragma unroll
        for (int b = 0; b < 8; b++)
#pragma unroll
            for (int c = 0; c < 4; c++) acc[a][b][c] = 0.f;

    lg_stage(oW, row0, col0,  0, smu + 0*LGS_SLOT, tid); cp_commit();
    lg_stage(oW, row0, col0, 32, smu + 1*LGS_SLOT, tid); cp_commit();
    lg_stage(oW, row0, col0, 64, smu + 2*LGS_SLOT, tid); cp_commit();

    const uint32_t b16 = smu + LGS_B16;
    for (int c = 0; c < 16; ++c){
        asm volatile("cp.async.wait_group 2;");
        __syncthreads();
        uint32_t slot = smu + (c & 3)*LGS_SLOT;

        // warp-local convert: rows warp_n*64 .. +63 of B32 -> B16 (warp_m
        // duplicates write identical values; benign)
        {
            const char* base = smem + (slot - smu) + 8192 + warp_n*64*128;
#pragma unroll
            for (int i = 0; i < 16; ++i){
                int row_local = (lane >> 3) + i*4;
                int seg = lane & 7;
                float4 v = *reinterpret_cast<const float4*>(base + row_local*128 + seg*16);
                __half hv[4] = {__float2half_rn(v.x), __float2half_rn(v.y),
                                __float2half_rn(v.z), __float2half_rn(v.w)};
                int nrow = warp_n*64 + row_local;
                int cc = seg >> 1, sub = (seg & 1)*8;
                *reinterpret_cast<uint2*>(smem + (b16 - smu) + nrow*64 +
                    ((uint32_t)(cc ^ (nrow&3)) << 4) + sub) = *reinterpret_cast<uint2*>(hv);
            }
        }
        __syncwarp();

        sc_chunk2(slot, b16, warp_m, warp_n, lane, acc);

        if (c + 3 < 16)
            lg_stage(oW, row0, col0, (c+3)*32, smu + ((c+3) & 3)*LGS_SLOT, tid);
        cp_commit();
    }

#pragma unroll
    for (int mt = 0; mt < 4; ++mt){
#pragma unroll
        for (int h = 0; h < 2; ++h){
            int m = row0 + warp_m*64 + mt*16 + h*8 + (lane>>2);
#pragma unroll
            for (int nt = 0; nt < 8; ++nt){
                int c = col0 + warp_n*64 + nt*8 + 2*(lane&3);
                float2 v = make_float2(acc[mt][nt][2*h+0] + ob[c],
                                       acc[mt][nt][2*h+1] + ob[c+1]);
                *(float2*)(out + (size_t)m * VOCAB + c) = v;
            }
        }
    }
}

// ============================================================================
// Gates: fp16 hi/lo 3-term MMA. CTA 128x128, split-K=6 (chunks of 384).
// ============================================================================
#define GT_STAGE 32768
#define GT_SMEM  (2*GT_STAGE)

__device__ __forceinline__ void gt_stage(int row0, int col0, int k0,
                                         uint32_t smb, int tid)
{
#pragma unroll
    for (int rep = 0; rep < 2; ++rep){
        int idx = tid + rep*256;
        int row = idx >> 2, c = idx & 3;
        uint32_t off = row*64 + ((uint32_t)(c ^ (row & 3)) << 4);
        size_t ea = (size_t)(row0 + row)*XDIM + k0 + c*8;
        size_t eb = (size_t)(col0 + row)*XDIM + k0 + c*8;
        cpasync16(smb +         off, g_xh  + ea);
        cpasync16(smb +  8192 + off, g_xl  + ea);
        cpasync16(smb + 16384 + off, g_gwh + eb);
        cpasync16(smb + 24576 + off, g_gwl + eb);
    }
}

__global__ __launch_bounds__(256,1) void gates_mma()
{
    extern __shared__ char smem[];
    uint32_t smu = (uint32_t)__cvta_generic_to_shared(smem);
    const int tid = threadIdx.x, lane = tid & 31, wid = tid >> 5;
    const int warp_m = wid & 3, warp_n = wid >> 2;  // 4 x 2, warp tile 32x64
    const int row0 = blockIdx.x * 128, col0 = blockIdx.y * 128;
    const int kbeg = blockIdx.z * (XDIM / NKC);     // 384 per chunk

    float acc[2][8][4];
#pragma unroll
    for (int a = 0; a < 2; a++)
#pragma unroll
        for (int b = 0; b < 8; b++)
#pragma unroll
            for (int c = 0; c < 4; c++) acc[a][b][c] = 0.f;

    gt_stage(row0, col0, kbeg, smu, tid); cp_commit();
    const int nit = (XDIM / NKC) / 32;   // 12
    for (int it = 0; it < nit; ++it){
        if (it + 1 < nit){
            gt_stage(row0, col0, kbeg + (it+1)*32, smu + ((it+1)&1)*GT_STAGE, tid);
            cp_commit();
            asm volatile("cp.async.wait_group 1;");
        } else {
            asm volatile("cp.async.wait_group 0;");
        }
        __syncthreads();
        uint32_t buf = smu + (it&1)*GT_STAGE;
#pragma unroll
        for (int s = 0; s < 2; ++s){
            uint32_t ah[2][4], al[2][4];
#pragma unroll
            for (int mt = 0; mt < 2; ++mt){
                int row = warp_m*32 + mt*16 + ((lane>>3)&1)*8 + (lane&7);
                int chunk = 2*s + (lane>>4);
                uint32_t addr = buf + row*64 + ((uint32_t)(chunk ^ (row&3)) << 4);
                ldsm4(ah[mt], addr);
                ldsm4(al[mt], addr + 8192);
            }
#pragma unroll
            for (int g = 0; g < 4; ++g){
                int nrow = warp_n*64 + g*16 + ((lane>>4)<<3) + (lane&7);
                int chunk = 2*s + ((lane>>3)&1);
                uint32_t baddr = buf + 16384 + nrow*64 + ((uint32_t)(chunk ^ (nrow&3)) << 4);
                uint32_t bh[4], bl[4];
                ldsm4(bh, baddr);
                ldsm4(bl, baddr + 8192);
#pragma unroll
                for (int mt = 0; mt < 2; ++mt){
                    mma16816h(acc[mt][2*g+0], ah[mt], bh+0);
                    mma16816h(acc[mt][2*g+0], ah[mt], bl+0);
                    mma16816h(acc[mt][2*g+0], al[mt], bh+0);
                    mma16816h(acc[mt][2*g+1], ah[mt], bh+2);
                    mma16816h(acc[mt][2*g+1], ah[mt], bl+2);
                    mma16816h(acc[mt][2*g+1], al[mt], bh+2);
                }
            }
        }
        __syncthreads();
    }

#pragma unroll
    for (int mt = 0; mt < 2; ++mt){
        int m = row0 + warp_m*32 + mt*16 + (lane>>2);
#pragma unroll
        for (int nt = 0; nt < 8; ++nt){
            int c = col0 + warp_n*64 + nt*8 + 2*(lane&3);
            float* d0 = g_gatesp + ((size_t)blockIdx.z * BATCH + m) * GDIM + c;
            float* d1 = g_gatesp + ((size_t)blockIdx.z * BATCH + m + 8) * GDIM + c;
            d0[0] = acc[mt][nt][0]; d0[1] = acc[mt][nt][1];
            d1[0] = acc[mt][nt][2]; d1[1] = acc[mt][nt][3];
        }
    }
}

// ============================================================================
// hpart: fp16 hi/lo 3-term MMA.  g_hpb[b, m] = b1[m] + h0 @ W1[:,1024:]^T
// ============================================================================
__device__ __forceinline__ void hp_stage(int row0, int col0, int k0,
                                         uint32_t smb, int tid)
{
#pragma unroll
    for (int rep = 0; rep < 2; ++rep){
        int idx = tid + rep*256;
        int row = idx >> 2, c = idx & 3;
        uint32_t off = row*64 + ((uint32_t)(c ^ (row & 3)) << 4);
        size_t ea = (size_t)(row0 + row)*HDIM + k0 + c*8;
        size_t eb = (size_t)(col0 + row)*HDIM + k0 + c*8;
        cpasync16(smb +         off, g_h0h  + ea);
        cpasync16(smb +  8192 + off, g_h0l  + ea);
        cpasync16(smb + 16384 + off, g_w1kh + eb);
        cpasync16(smb + 24576 + off, g_w1kl + eb);
    }
}

__global__ __launch_bounds__(256,1) void hpart_mma(const float* __restrict__ b1)
{
    extern __shared__ char smem[];
    uint32_t smu = (uint32_t)__cvta_generic_to_shared(smem);
    const int tid = threadIdx.x, lane = tid & 31, wid = tid >> 5;
    const int warp_m = wid & 3, warp_n = wid >> 2;  // 4 x 2, warp tile 32x64
    const int row0 = blockIdx.x * 128, col0 = blockIdx.y * 128;

    float acc[2][8][4];
#pragma unroll
    for (int a = 0; a < 2; a++)
#pragma unroll
        for (int b = 0; b < 8; b++)
#pragma unroll
            for (int c = 0; c < 4; c++) acc[a][b][c] = 0.f;

    hp_stage(row0, col0, 0, smu, tid); cp_commit();
    const int nit = HDIM / 32;   // 16
    for (int it = 0; it < nit; ++it){
        if (it + 1 < nit){
            hp_stage(row0, col0, (it+1)*32, smu + ((it+1)&1)*GT_STAGE, tid);
            cp_commit();
            asm volatile("cp.async.wait_group 1;");
        } else {
            asm volatile("cp.async.wait_group 0;");
        }
        __syncthreads();
        uint32_t buf = smu + (it&1)*GT_STAGE;
#pragma unroll
        for (int s = 0; s < 2; ++s){
            uint32_t ah[2][4], al[2][4];
#pragma unroll
            for (int mt = 0; mt < 2; ++mt){
                int row = warp_m*32 + mt*16 + ((lane>>3)&1)*8 + (lane&7);
                int chunk = 2*s + (lane>>4);
                uint32_t addr = buf + row*64 + ((uint32_t)(chunk ^ (row&3)) << 4);
                ldsm4(ah[mt], addr);
                ldsm4(al[mt], addr + 8192);
            }
#pragma unroll
            for (int g = 0; g < 4; ++g){
                int nrow = warp_n*64 + g*16 + ((lane>>4)<<3) + (lane&7);
                int chunk = 2*s + ((lane>>3)&1);
                uint32_t baddr = buf + 16384 + nrow*64 + ((uint32_t)(chunk ^ (nrow&3)) << 4);
                uint32_t bh[4], bl[4];
                ldsm4(bh, baddr);
                ldsm4(bl, baddr + 8192);
#pragma unroll
                for (int mt = 0; mt < 2; ++mt){
                    mma16816h(acc[mt][2*g+0], ah[mt], bh+0);
                    mma16816h(acc[mt][2*g+0], ah[mt], bl+0);
                    mma16816h(acc[mt][2*g+0], al[mt], bh+0);
                    mma16816h(acc[mt][2*g+1], ah[mt], bh+2);
                    mma16816h(acc[mt][2*g+1], ah[mt], bl+2);
                    mma16816h(acc[mt][2*g+1], al[mt], bh+2);
                }
            }
        }
        __syncthreads();
    }

#pragma unroll
    for (int mt = 0; mt < 2; ++mt){
        int m = row0 + warp_m*32 + mt*16 + (lane>>2);
#pragma unroll
        for (int nt = 0; nt < 8; ++nt){
            int c = col0 + warp_n*64 + nt*8 + 2*(lane&3);
            float ba = b1[c], bb = b1[c+1];
            float* d0 = g_hpb + (size_t)m * H3 + c;
            float* d1 = g_hpb + (size_t)(m+8) * H3 + c;
            d0[0] = acc[mt][nt][0] + ba; d0[1] = acc[mt][nt][1] + bb;
            d1[0] = acc[mt][nt][2] + ba; d1[1] = acc[mt][nt][3] + bb;
        }
    }
}

// ============================================================================
// conv_enc (16 floats/thread) + merged weight conversion (no oW)
// ============================================================================
__global__ void conv_enc_kernel(const float* __restrict__ enc){
    size_t i = (size_t)blockIdx.x * 256 + threadIdx.x;    // group of 16 floats
    const float4* s = reinterpret_cast<const float4*>(enc) + i*4;
    uint4* d = reinterpret_cast<uint4*>(g_encf) + i*2;
    float4 s0 = s[0], s1 = s[1], s2 = s[2], s3 = s[3];
    d[0] = cvt8_f16(s0, s1);
    d[1] = cvt8_f16(s2, s3);
}

// merged: w1f | w1k hi/lo | gw hi/lo | h0 hi/lo  (8 elems per thread)
#define CW_A 196608u                    /* w1f groups: 1536*128 */
#define CW_B (CW_A + 98304u)            /* w1k:  1536*64  */
#define CW_D (CW_B + 589824u)           /* gw: 2048*288   */
#define CW_E (CW_D + 16384u)            /* h0: 16384      */

__global__ void conv_weights(const float* __restrict__ W1,
                             const float* __restrict__ Wih,
                             const float* __restrict__ Whh,
                             const float* __restrict__ hid)
{
    uint32_t i = blockIdx.x * 256 + threadIdx.x;
    if (i < CW_A){
        int row = i / 128, c8 = i % 128;
        const float4* s = reinterpret_cast<const float4*>(W1 + (size_t)row * H3 + c8 * 8);
        reinterpret_cast<uint4*>(g_w1f)[(size_t)row * 128 + c8] = cvt8_f16(s[0], s[1]);
    } else if (i < CW_B){
        uint32_t j = i - CW_A;
        int row = j / 64, c = j % 64;
        const float4* s = reinterpret_cast<const float4*>(W1 + (size_t)row * H3 + 1024 + c * 8);
        uint4 uh, ul; cvt8_hl(s[0], s[1], uh, ul);
        reinterpret_cast<uint4*>(g_w1kh)[(size_t)row * 64 + c] = uh;
        reinterpret_cast<uint4*>(g_w1kl)[(size_t)row * 64 + c] = ul;
    } else if (i < CW_D){
        uint32_t j = i - CW_B;
        int row = j / 288, c8 = j % 288;
        const float* src = (c8 < 224) ? (Wih + (size_t)row * 1792 + c8 * 8)
                                      : (Whh + (size_t)row * HDIM + (c8 - 224) * 8);
        const float4* s = reinterpret_cast<const float4*>(src);
        uint4 uh, ul; cvt8_hl(s[0], s[1], uh, ul);
        reinterpret_cast<uint4*>(g_gwh)[(size_t)row * 288 + c8] = uh;
        reinterpret_cast<uint4*>(g_gwl)[(size_t)row * 288 + c8] = ul;
    } else {
        uint32_t j = i - CW_D;
        const float4* s = reinterpret_cast<const float4*>(hid) + (size_t)j*2;
        uint4 uh, ul; cvt8_hl(s[0], s[1], uh, ul);
        reinterpret_cast<uint4*>(g_h0h)[j] = uh;
        reinterpret_cast<uint4*>(g_h0l)[j] = ul;
    }
}

// ============================================================================
// fused: softmax + context (fp16 enc) + fill x (fp16 hi/lo directly)
// ============================================================================
__global__ __launch_bounds__(256) void attn_finish(
    const float* __restrict__ b2, const int* __restrict__ ids,
    const float* __restrict__ emb, const float* __restrict__ hid)
{
    int b = blockIdx.x, t = threadIdx.x;
    __shared__ float att[128];
    __shared__ float red[128];

    if (t < 128){
        float sc = b2[0];
#pragma unroll
        for (int ct = 0; ct < NCTS; ct++)
            sc += g_scorep[(size_t)ct * ROWS + t * BATCH + b];
        att[t] = sc;
        red[t] = sc;
    }
    __syncthreads();
    for (int off = 64; off > 0; off >>= 1){
        if (t < off) red[t] = fmaxf(red[t], red[t+off]);
        __syncthreads();
    }
    float mx = red[0];
    __syncthreads();
    if (t < 128){
        float e = expf(att[t] - mx);
        att[t] = e;
        red[t] = e;
    }
    __syncthreads();
    for (int off = 64; off > 0; off >>= 1){
        if (t < off) red[t] += red[t+off];
        __syncthreads();
    }
    float inv = 1.0f / red[0];
    __syncthreads();
    if (t < 128) att[t] *= inv;
    __syncthreads();

    __half* xh = g_xh + (size_t)b * XDIM;
    __half* xl = g_xl + (size_t)b * XDIM;

    float a0=0.f, a1=0.f, a2=0.f, a3=0.f;
    const __half* ep = g_encf + (size_t)b * 1024 + 4*t;
    for (int s = 0; s < 128; s++){
        float a = att[s];
        uint2 raw = *reinterpret_cast<const uint2*>(ep + (size_t)s * BATCH * 1024);
        __half2 p0 = *reinterpret_cast<__half2*>(&raw.x);
        __half2 p1 = *reinterpret_cast<__half2*>(&raw.y);
        float2 f0 = __half22float2(p0), f1 = __half22float2(p1);
        a0 += a*f0.x; a1 += a*f0.y; a2 += a*f1.x; a3 += a*f1.y;
    }
    store4_hl(xh + EDIM + 4*t, xl + EDIM + 4*t, make_float4(a0, a1, a2, a3));

    if (t < 64){
        int id = ids[b];
        float4 ev = *reinterpret_cast<const float4*>(emb + (size_t)id * EDIM + 4*t);
        store4_hl(xh + 4*t, xl + 4*t, ev);
    }
    if (t < 128){
        float4 hv = *reinterpret_cast<const float4*>(hid + (size_t)b * HDIM + 4*t);
        store4_hl(xh + 1280 + 4*t, xl + 1280 + 4*t, hv);
        store4_hl(xh + 1792 + 4*t, xl + 1792 + 4*t, hv);
    }
}

// ============================================================================
// LSTM cell
// ============================================================================
__global__ void lstm_kernel(const float* __restrict__ bih, const float* __restrict__ bhh,
                            const float* __restrict__ cell, float* __restrict__ out)
{
    int b = blockIdx.x, j = threadIdx.x;
    float g4[4];
#pragma unroll
    for (int q = 0; q < 4; q++) {
        int c = q * HDIM + j;
        float v = bih[c] + bhh[c];
#pragma unroll
        for (int kc = 0; kc < NKC; kc++)
            v += g_gatesp[((size_t)kc * BATCH + b) * GDIM + c];
        g4[q] = v;
    }
    float ig = sigmf(g4[0]), fg = sigmf(g4[1]);
    float gg = tanhf(g4[2]), og = sigmf(g4[3]);
    float c0 = cell[(size_t)b * HDIM + j];
    float cn = fg * c0 + ig * gg;
    float hn = og * tanhf(cn);
    size_t hbase = (size_t)VOCAB * BATCH;
    out[hbase + (size_t)b * HDIM + j] = hn;
    out[hbase + (size_t)BATCH * HDIM + (size_t)b * HDIM + j] = cn;
    g_hf[b * HDIM + j] = __float2half_rn(hn);
}

// ============================================================================
extern "C" void kernel_launch(void* const* d_in, const int* in_sizes, int n_in,
                              void* d_out, int out_size)
{
    const int*   ids = (const int*)d_in[0];
    const float* enc = (const float*)d_in[1];
    const float* hid = (const float*)d_in[2];
    const float* cel = (const float*)d_in[3];
    const float* emb = (const float*)d_in[4];
    const float* Wih = (const float*)d_in[5];
    const float* Whh = (const float*)d_in[6];
    const float* bih = (const float*)d_in[7];
    const float* bhh = (const float*)d_in[8];
    const float* W1  = (const float*)d_in[9];
    const float* b1  = (const float*)d_in[10];
    const float* w2  = (const float*)d_in[11];
    const float* b2  = (const float*)d_in[12];
    const float* oW  = (const float*)d_in[13];
    const float* ob  = (const float*)d_in[14];
    float* out = (float*)d_out;

    cudaFuncSetAttribute(scorer_fp16, cudaFuncAttributeMaxDynamicSharedMemorySize, SC2_SMEM);
    cudaFuncSetAttribute(logits_fp16, cudaFuncAttributeMaxDynamicSharedMemorySize, LG_SMEM);
    cudaFuncSetAttribute(gates_mma,   cudaFuncAttributeMaxDynamicSharedMemorySize, GT_SMEM);
    cudaFuncSetAttribute(hpart_mma,   cudaFuncAttributeMaxDynamicSharedMemorySize, GT_SMEM);

    conv_enc_kernel<<<(ROWS * KENC) / 4096, 256>>>(enc);
    conv_weights<<<CW_E / 256, 256>>>(W1, Wih, Whh, hid);
    hpart_mma<<<dim3(BATCH / 128, H3 / 128), 256, GT_SMEM>>>(b1);

    scorer_fp16<<<dim3(NCTS, ROWS / 128), 128, SC2_SMEM>>>(w2);
    attn_finish<<<BATCH, 256>>>(b2, ids, emb, hid);
    gates_mma<<<dim3(BATCH / 128, GDIM / 128, NKC), 256, GT_SMEM>>>();
    lstm_kernel<<<BATCH, 512>>>(bih, bhh, cel, out);
    logits_fp16<<<dim3(BATCH / 128, VOCAB / 256), 256, LG_SMEM>>>(oW, ob, out);
}